// round 15
// baseline (speedup 1.0000x reference)
#include <cuda_runtime.h>
#include <cuda_bf16.h>
#include <mma.h>
#include <math.h>

using namespace nvcuda;

#define NA 20000
#define NE 320000
#define F 128
#define F3 (3*F)
#define NRBF 20
#define NCONV 3
#define CUTOFF 5.0f
#define PI_F 3.14159265358979323846f

// weight-split buffer offsets (elements)
#define OFF_W1   0
#define OFF_W2   49152
#define OFF_U    196608
#define OFF_V    245760
#define OFF_WS1  294912
#define OFF_WS2  393216
#define OFF_WR1  540672
#define OFF_WF1  557056
#define OFF_WF2  565248
#define W_TOTAL  581632

// ---------------- scratch (device globals) ----------------
__device__ float g_s[NA * F];
__device__ float g_va[NA * F3];
__device__ float g_vb[NA * F3];
__device__ float g_t[NA * F];
__device__ float g_phi[NA * F3];
__device__ float g_uv[NA * F3];
__device__ float g_vv[NA * F3];
__device__ float g_split[NA * F3];
__device__ float g_unit[NE * 3];
__device__ float g_fcut[NE];
__device__ float g_rbf[NE * NRBF];
__device__ float g_fea[NA * 64];
__device__ __nv_bfloat16 g_wh[W_TOTAL];
__device__ __nv_bfloat16 g_wl[W_TOTAL];
// bf16-chained activation buffers
__device__ __nv_bfloat16 g_th[NA * F],  g_tl[NA * F];       // t
__device__ __nv_bfloat16 g_vh[NA * F3], g_vl[NA * F3];      // vout
__device__ __nv_bfloat16 g_ch[NA * 2 * F], g_cl[NA * 2 * F];// cat
__device__ int g_cnt[NA + 1];
__device__ int g_pos[NA];
__device__ int g_off[NA + 1];
__device__ int g_csr[NE];

__device__ __forceinline__ float silu_f(float x) { return x / (1.0f + expf(-x)); }

__device__ __forceinline__ void bsplit(float x, __nv_bfloat16& h, __nv_bfloat16& l) {
    h = __float2bfloat16(x);
    l = __float2bfloat16(x - __bfloat162float(h));
}

// ---------------- pre-split ALL weights to bf16 hi/lo (once per launch) ----
__global__ void wconv_all_kernel(const float* __restrict__ W1, const float* __restrict__ W2,
                                 const float* __restrict__ U,  const float* __restrict__ V,
                                 const float* __restrict__ Ws1, const float* __restrict__ Ws2,
                                 const float* __restrict__ Wr1, const float* __restrict__ Wf1,
                                 const float* __restrict__ Wf2) {
    int t = blockIdx.x * blockDim.x + threadIdx.x;
    if (t >= W_TOTAL) return;
    float x;
    if      (t < OFF_W2)  x = W1[t - OFF_W1];
    else if (t < OFF_U)   x = W2[t - OFF_W2];
    else if (t < OFF_V)   x = U[t - OFF_U];
    else if (t < OFF_WS1) x = V[t - OFF_V];
    else if (t < OFF_WS2) x = Ws1[t - OFF_WS1];
    else if (t < OFF_WR1) x = Ws2[t - OFF_WS2];
    else if (t < OFF_WF1) x = Wr1[t - OFF_WR1];
    else if (t < OFF_WF2) x = Wf1[t - OFF_WF1];
    else                  x = Wf2[t - OFF_WF2];
    bsplit(x, g_wh[t], g_wl[t]);
}

// ---------------- zero counters ----------------
__global__ void zero_cnt_kernel() {
    int t = blockIdx.x * blockDim.x + threadIdx.x;
    if (t <= NA) g_cnt[t] = 0;
    if (t < NA) g_pos[t] = 0;
}

// ---------------- edge geometry (Chebyshev rbf) + filtered degree count ----
__global__ void edge_geom_kernel(const float* __restrict__ xyz,
                                 const int* __restrict__ nbrs) {
    int e = blockIdx.x * blockDim.x + threadIdx.x;
    if (e >= NE) return;
    int i = nbrs[2 * e], j = nbrs[2 * e + 1];
    float dx = xyz[3 * j + 0] - xyz[3 * i + 0];
    float dy = xyz[3 * j + 1] - xyz[3 * i + 1];
    float dz = xyz[3 * j + 2] - xyz[3 * i + 2];
    float d = sqrtf(dx * dx + dy * dy + dz * dz + 1e-12f);
    float inv = 1.0f / d;
    g_unit[3 * e + 0] = dx * inv;
    g_unit[3 * e + 1] = dy * inv;
    g_unit[3 * e + 2] = dz * inv;
    float a = PI_F * d / CUTOFF;
    float s1, c1;
    sincosf(a, &s1, &c1);
    float fc = (d < CUTOFF) ? 0.5f * (c1 + 1.0f) : 0.0f;
    g_fcut[e] = fc;
    float two_c = 2.0f * c1;
    float sk_m1 = 0.0f;
    float sk = s1;
    g_rbf[e * NRBF + 0] = sk * inv;
#pragma unroll
    for (int k = 1; k < NRBF; k++) {
        float sk_p1 = two_c * sk - sk_m1;
        sk_m1 = sk;
        sk = sk_p1;
        g_rbf[e * NRBF + k] = sk * inv;
    }
    if (fc > 0.0f) atomicAdd(&g_cnt[i], 1);
}

// ---------------- exclusive scan over degrees ----------------
__global__ void scan_kernel() {
    __shared__ int part[1024];
    const int CH = (NA + 1023) / 1024;
    int t = threadIdx.x;
    int base = t * CH;
    int s = 0;
    for (int k = 0; k < CH; k++) {
        int idx = base + k;
        if (idx < NA) s += g_cnt[idx];
    }
    part[t] = s;
    __syncthreads();
    for (int off = 1; off < 1024; off <<= 1) {
        int v = (t >= off) ? part[t - off] : 0;
        __syncthreads();
        part[t] += v;
        __syncthreads();
    }
    int run = (t == 0) ? 0 : part[t - 1];
    for (int k = 0; k < CH; k++) {
        int idx = base + k;
        if (idx < NA) {
            g_off[idx] = run;
            run += g_cnt[idx];
        }
    }
    if (t == 0) g_off[NA] = part[1023];
}

// ---------------- fill CSR (filtered) ----------------
__global__ void csr_fill_kernel(const int* __restrict__ nbrs) {
    int e = blockIdx.x * blockDim.x + threadIdx.x;
    if (e >= NE) return;
    if (g_fcut[e] <= 0.0f) return;
    int i = nbrs[2 * e];
    int p = atomicAdd(&g_pos[i], 1);
    g_csr[g_off[i] + p] = e;
}

// ---------------- init: s = embed[z], va = 0 (+ bf16 v splits) -------------
__global__ void embed_init_kernel(const int* __restrict__ z,
                                  const float* __restrict__ embed) {
    int t = blockIdx.x * blockDim.x + threadIdx.x;
    if (t < NA * F) {
        int n = t / F, f = t % F;
        g_s[t] = embed[z[n] * F + f];
    }
    if (t < NA * F3) g_va[t] = 0.0f;
}

// ---------------- per-atom edge gather (R9 loop untouched) -----------------
// epilogue additionally writes bf16 hi/lo split of vout for U/V GEMMs.
__global__ void __launch_bounds__(128)
edge_gather_kernel(const int* __restrict__ nbrs,
                   const float* __restrict__ Wd,
                   const float* __restrict__ bd,
                   const float* __restrict__ vin,
                   float* __restrict__ vout) {
    const int a = blockIdx.x;
    const int t = threadIdx.x;

    float wd0[NRBF], wd1[NRBF], wd2[NRBF];
#pragma unroll
    for (int k = 0; k < NRBF; k++) {
        wd0[k] = Wd[k * F3 + t];
        wd1[k] = Wd[k * F3 + F + t];
        wd2[k] = Wd[k * F3 + 2 * F + t];
    }
    const float b0 = bd[t], b1 = bd[F + t], b2 = bd[2 * F + t];

    float acc_s = 0.f, acc_v0 = 0.f, acc_v1 = 0.f, acc_v2 = 0.f;

    const int beg = g_off[a], end = g_off[a + 1];
    int idx = beg;

    for (; idx + 2 <= end; idx += 2) {
        const int e0 = g_csr[idx];
        const int e1 = g_csr[idx + 1];
        const int j0 = __ldg(&nbrs[2 * e0 + 1]) * F3;
        const int j1 = __ldg(&nbrs[2 * e1 + 1]) * F3;
        const float fc0 = g_fcut[e0];
        const float fc1 = g_fcut[e1];
        const float u0x = g_unit[3 * e0 + 0], u0y = g_unit[3 * e0 + 1], u0z = g_unit[3 * e0 + 2];
        const float u1x = g_unit[3 * e1 + 0], u1y = g_unit[3 * e1 + 1], u1z = g_unit[3 * e1 + 2];

        const float p00 = g_phi[j0 + t], p01 = g_phi[j0 + F + t], p02 = g_phi[j0 + 2 * F + t];
        const float p10 = g_phi[j1 + t], p11 = g_phi[j1 + F + t], p12 = g_phi[j1 + 2 * F + t];
        const float va0 = vin[j0 + t],  va1 = vin[j0 + F + t],  va2 = vin[j0 + 2 * F + t];
        const float vb0 = vin[j1 + t],  vb1 = vin[j1 + F + t],  vb2 = vin[j1 + 2 * F + t];

        const float4* r0p = reinterpret_cast<const float4*>(&g_rbf[(size_t)e0 * NRBF]);
        const float4* r1p = reinterpret_cast<const float4*>(&g_rbf[(size_t)e1 * NRBF]);

        float w00 = b0, w01 = b1, w02 = b2;
        float w10 = b0, w11 = b1, w12 = b2;
#pragma unroll
        for (int q = 0; q < NRBF / 4; q++) {
            float4 r0 = r0p[q];
            float4 r1 = r1p[q];
            int k = 4 * q;
            w00 += r0.x * wd0[k] + r0.y * wd0[k + 1] + r0.z * wd0[k + 2] + r0.w * wd0[k + 3];
            w10 += r1.x * wd0[k] + r1.y * wd0[k + 1] + r1.z * wd0[k + 2] + r1.w * wd0[k + 3];
            w01 += r0.x * wd1[k] + r0.y * wd1[k + 1] + r0.z * wd1[k + 2] + r0.w * wd1[k + 3];
            w11 += r1.x * wd1[k] + r1.y * wd1[k + 1] + r1.z * wd1[k + 2] + r1.w * wd1[k + 3];
            w02 += r0.x * wd2[k] + r0.y * wd2[k + 1] + r0.z * wd2[k + 2] + r0.w * wd2[k + 3];
            w12 += r1.x * wd2[k] + r1.y * wd2[k + 1] + r1.z * wd2[k + 2] + r1.w * wd2[k + 3];
        }
        const float i00 = p00 * w00 * fc0, i01 = p01 * w01 * fc0, i02 = p02 * w02 * fc0;
        const float i10 = p10 * w10 * fc1, i11 = p11 * w11 * fc1, i12 = p12 * w12 * fc1;

        acc_s  += i01 + i11;
        acc_v0 += u0x * i02 + i00 * va0 + u1x * i12 + i10 * vb0;
        acc_v1 += u0y * i02 + i00 * va1 + u1y * i12 + i10 * vb1;
        acc_v2 += u0z * i02 + i00 * va2 + u1z * i12 + i10 * vb2;
    }

    if (idx < end) {
        const int e0 = g_csr[idx];
        const int j0 = __ldg(&nbrs[2 * e0 + 1]) * F3;
        const float fc0 = g_fcut[e0];
        const float u0x = g_unit[3 * e0 + 0], u0y = g_unit[3 * e0 + 1], u0z = g_unit[3 * e0 + 2];
        const float p00 = g_phi[j0 + t], p01 = g_phi[j0 + F + t], p02 = g_phi[j0 + 2 * F + t];
        const float va0 = vin[j0 + t],  va1 = vin[j0 + F + t],  va2 = vin[j0 + 2 * F + t];
        const float4* r0p = reinterpret_cast<const float4*>(&g_rbf[(size_t)e0 * NRBF]);
        float w00 = b0, w01 = b1, w02 = b2;
#pragma unroll
        for (int q = 0; q < NRBF / 4; q++) {
            float4 r0 = r0p[q];
            int k = 4 * q;
            w00 += r0.x * wd0[k] + r0.y * wd0[k + 1] + r0.z * wd0[k + 2] + r0.w * wd0[k + 3];
            w01 += r0.x * wd1[k] + r0.y * wd1[k + 1] + r0.z * wd1[k + 2] + r0.w * wd1[k + 3];
            w02 += r0.x * wd2[k] + r0.y * wd2[k + 1] + r0.z * wd2[k + 2] + r0.w * wd2[k + 3];
        }
        const float i00 = p00 * w00 * fc0, i01 = p01 * w01 * fc0, i02 = p02 * w02 * fc0;
        acc_s  += i01;
        acc_v0 += u0x * i02 + i00 * va0;
        acc_v1 += u0y * i02 + i00 * va1;
        acc_v2 += u0z * i02 + i00 * va2;
    }

    g_s[a * F + t] += acc_s;
    const float o0 = vin[a * F3 + t]         + acc_v0;
    const float o1 = vin[a * F3 + F + t]     + acc_v1;
    const float o2 = vin[a * F3 + 2 * F + t] + acc_v2;
    vout[a * F3 + t]         = o0;
    vout[a * F3 + F + t]     = o1;
    vout[a * F3 + 2 * F + t] = o2;
    bsplit(o0, g_vh[a * F3 + t],         g_vl[a * F3 + t]);
    bsplit(o1, g_vh[a * F3 + F + t],     g_vl[a * F3 + F + t]);
    bsplit(o2, g_vh[a * F3 + 2 * F + t], g_vl[a * F3 + 2 * F + t]);
}

// ---------------- vnorm + concat (writes bf16 split cat) ----------------
__global__ void vnorm_cat_kernel() {
    int t = blockIdx.x * blockDim.x + threadIdx.x;
    if (t >= NA * F) return;
    int n = t / F, f = t % F;
    bsplit(g_s[t], g_ch[n * 2 * F + f], g_cl[n * 2 * F + f]);
    float a = g_vv[n * F3 + f];
    float b = g_vv[n * F3 + F + f];
    float c = g_vv[n * F3 + 2 * F + f];
    float nm = sqrtf(a * a + b * b + c * c + 1e-12f);
    bsplit(nm, g_ch[n * 2 * F + F + f], g_cl[n * 2 * F + F + f]);
}

// ---------------- gated update ----------------
__global__ void update_kernel(float* __restrict__ v) {
    int t = blockIdx.x * blockDim.x + threadIdx.x;
    if (t >= NA * F) return;
    int n = t / F, f = t % F;
    float avv = g_split[n * F3 + f];
    float asv = g_split[n * F3 + F + f];
    float ass = g_split[n * F3 + 2 * F + f];
    float dot = 0.0f;
#pragma unroll
    for (int d = 0; d < 3; d++) {
        float u = g_uv[n * F3 + d * F + f];
        float w = g_vv[n * F3 + d * F + f];
        dot += u * w;
        v[n * F3 + d * F + f] += u * avv;
    }
    g_s[t] += dot * asv + ass;
}

// ============== Tensor-core GEMM: BM=64, BN=128, BK=16, 8 warps =============
// W always pre-split bf16 hi/lo. ABF: A given as bf16 hi/lo (no cvt).
// OBF: epilogue writes bf16 hi/lo split (after bias/act) instead of fp32.
#define WA_LD 24
#define WB_LD 136
#define WC_LD 20

template <int ACT, bool DIRECT, bool ABF, bool OBF>
__global__ void __launch_bounds__(256)
wgemm_kernel(const float* __restrict__ A,
             const __nv_bfloat16* __restrict__ Ah, const __nv_bfloat16* __restrict__ Al,
             const __nv_bfloat16* __restrict__ Wh, const __nv_bfloat16* __restrict__ Wl,
             const float* __restrict__ bias, float* __restrict__ C,
             __nv_bfloat16* __restrict__ Ch, __nv_bfloat16* __restrict__ Cl,
             int M, int N, int K) {
    constexpr int BM = 64, BN = 128, BK = 16;
    __shared__ __nv_bfloat16 As_hi[BM][WA_LD];
    __shared__ __nv_bfloat16 As_lo[BM][WA_LD];
    __shared__ __nv_bfloat16 Bs_hi[BK][WB_LD];
    __shared__ __nv_bfloat16 Bs_lo[BK][WB_LD];
    __shared__ float cstage[8][16 * WC_LD];

    const int tid = threadIdx.x;
    const int wid = tid >> 5;
    const int m0 = blockIdx.y * BM, n0 = blockIdx.x * BN;

    const int arow = tid >> 2, ak = (tid & 3) << 2;
    const bool aOK = (m0 + arow < M);
    const int brow = tid >> 4, bcol = (tid & 15) << 3;

    wmma::fragment<wmma::accumulator, 16, 16, 16, float> c[2][2];
#pragma unroll
    for (int i = 0; i < 2; i++)
#pragma unroll
        for (int j = 0; j < 2; j++)
            wmma::fill_fragment(c[i][j], 0.0f);

    const int wm = (wid >> 2) * 32;
    const int wn = (wid & 3) * 32;

    const int nk = K / BK;
    for (int kt = 0; kt < nk; kt++) {
        const int k0 = kt * BK;
        if (ABF) {
            const size_t aoff = (size_t)(m0 + arow) * K + k0 + ak;
            uint2 hv = make_uint2(0u, 0u), lv = make_uint2(0u, 0u);
            if (aOK) {
                hv = *reinterpret_cast<const uint2*>(Ah + aoff);
                lv = *reinterpret_cast<const uint2*>(Al + aoff);
            }
            *reinterpret_cast<uint2*>(&As_hi[arow][ak]) = hv;
            *reinterpret_cast<uint2*>(&As_lo[arow][ak]) = lv;
        } else {
            float buf[4];
            if (aOK) {
                *reinterpret_cast<float4*>(buf) =
                    *reinterpret_cast<const float4*>(A + (size_t)(m0 + arow) * K + k0 + ak);
            } else {
#pragma unroll
                for (int q = 0; q < 4; q++) buf[q] = 0.f;
            }
            __nv_bfloat16 h0, h1, h2, h3, l0, l1, l2, l3;
            bsplit(buf[0], h0, l0);
            bsplit(buf[1], h1, l1);
            bsplit(buf[2], h2, l2);
            bsplit(buf[3], h3, l3);
            __nv_bfloat162 hp0; hp0.x = h0; hp0.y = h1;
            __nv_bfloat162 hp1; hp1.x = h2; hp1.y = h3;
            __nv_bfloat162 lp0; lp0.x = l0; lp0.y = l1;
            __nv_bfloat162 lp1; lp1.x = l2; lp1.y = l3;
            *reinterpret_cast<__nv_bfloat162*>(&As_hi[arow][ak])     = hp0;
            *reinterpret_cast<__nv_bfloat162*>(&As_hi[arow][ak + 2]) = hp1;
            *reinterpret_cast<__nv_bfloat162*>(&As_lo[arow][ak])     = lp0;
            *reinterpret_cast<__nv_bfloat162*>(&As_lo[arow][ak + 2]) = lp1;
        }
        {
            const size_t woff = (size_t)(k0 + brow) * N + n0 + bcol;
            *reinterpret_cast<uint4*>(&Bs_hi[brow][bcol]) =
                *reinterpret_cast<const uint4*>(Wh + woff);
            *reinterpret_cast<uint4*>(&Bs_lo[brow][bcol]) =
                *reinterpret_cast<const uint4*>(Wl + woff);
        }
        __syncthreads();

        wmma::fragment<wmma::matrix_a, 16, 16, 16, __nv_bfloat16, wmma::row_major> ah[2], al[2];
        wmma::fragment<wmma::matrix_b, 16, 16, 16, __nv_bfloat16, wmma::row_major> bh[2], bl[2];
#pragma unroll
        for (int i = 0; i < 2; i++) {
            wmma::load_matrix_sync(ah[i], &As_hi[wm + i * 16][0], WA_LD);
            wmma::load_matrix_sync(al[i], &As_lo[wm + i * 16][0], WA_LD);
        }
#pragma unroll
        for (int j = 0; j < 2; j++) {
            wmma::load_matrix_sync(bh[j], &Bs_hi[0][wn + j * 16], WB_LD);
            wmma::load_matrix_sync(bl[j], &Bs_lo[0][wn + j * 16], WB_LD);
        }
#pragma unroll
        for (int i = 0; i < 2; i++)
#pragma unroll
            for (int j = 0; j < 2; j++) {
                wmma::mma_sync(c[i][j], ah[i], bh[j], c[i][j]);
                wmma::mma_sync(c[i][j], ah[i], bl[j], c[i][j]);
                wmma::mma_sync(c[i][j], al[i], bh[j], c[i][j]);
            }
        __syncthreads();
    }

    const int lane = tid & 31;
#pragma unroll
    for (int i = 0; i < 2; i++) {
        const int grow0 = m0 + wm + i * 16;
#pragma unroll
        for (int j = 0; j < 2; j++) {
            const int gcol0 = n0 + wn + j * 16;
            if (DIRECT && grow0 + 16 <= M) {
                wmma::store_matrix_sync(C + (size_t)grow0 * N + gcol0, c[i][j], N,
                                        wmma::mem_row_major);
            } else {
                wmma::store_matrix_sync(&cstage[wid][0], c[i][j], WC_LD, wmma::mem_row_major);
                __syncwarp();
#pragma unroll
                for (int e = 0; e < 8; e++) {
                    int el = e * 32 + lane;
                    int r = el >> 4, cc = el & 15;
                    int grow = grow0 + r;
                    if (grow < M) {
                        int gcol = gcol0 + cc;
                        float x = cstage[wid][r * WC_LD + cc] + (bias ? bias[gcol] : 0.f);
                        if (ACT == 1) x = silu_f(x);
                        if (OBF) {
                            __nv_bfloat16 h, l;
                            bsplit(x, h, l);
                            Ch[(size_t)grow * N + gcol] = h;
                            Cl[(size_t)grow * N + gcol] = l;
                        } else {
                            C[(size_t)grow * N + gcol] = x;
                        }
                    }
                }
                __syncwarp();
            }
        }
    }
}

// ---------------- fp32 SGEMM 64x128 (readout N=64 only) ----------------
template <int ACT>
__global__ void __launch_bounds__(128)
sgemm64_kernel(const float* __restrict__ A, const float* __restrict__ W,
               const float* __restrict__ bias, float* __restrict__ C,
               int M, int N, int K) {
    constexpr int BM = 64, BN = 128, BK = 8;
    __shared__ float As[2][BK][BM];
    __shared__ float Bs[2][BK][BN];
    const int tid = threadIdx.x;
    const int m0 = blockIdx.y * BM, n0 = blockIdx.x * BN;
    const int arow = tid >> 1, acol = (tid & 1) << 2;
    const int brow = tid >> 4, bcol = (tid & 15) << 3;
    const int tx = tid & 15, ty = tid >> 4;

    float acc[8][8] = {};
    float4 aR, bR0, bR1;
    const int gmA = m0 + arow;
    const bool aOK = (gmA < M);
    const bool bOK0 = (n0 + bcol < N);
    const bool bOK1 = (n0 + bcol + 4 < N);

    aR = aOK ? *reinterpret_cast<const float4*>(A + (size_t)gmA * K + acol)
             : make_float4(0.f, 0.f, 0.f, 0.f);
    bR0 = bOK0 ? *reinterpret_cast<const float4*>(W + (size_t)brow * N + n0 + bcol)
               : make_float4(0.f, 0.f, 0.f, 0.f);
    bR1 = bOK1 ? *reinterpret_cast<const float4*>(W + (size_t)brow * N + n0 + bcol + 4)
               : make_float4(0.f, 0.f, 0.f, 0.f);
    As[0][acol + 0][arow] = aR.x;
    As[0][acol + 1][arow] = aR.y;
    As[0][acol + 2][arow] = aR.z;
    As[0][acol + 3][arow] = aR.w;
    *reinterpret_cast<float4*>(&Bs[0][brow][bcol]) = bR0;
    *reinterpret_cast<float4*>(&Bs[0][brow][bcol + 4]) = bR1;
    __syncthreads();

    const int nk = K / BK;
    for (int kt = 0; kt < nk; kt++) {
        const int buf = kt & 1;
        if (kt + 1 < nk) {
            int k0 = (kt + 1) * BK;
            aR = aOK ? *reinterpret_cast<const float4*>(A + (size_t)gmA * K + k0 + acol)
                     : make_float4(0.f, 0.f, 0.f, 0.f);
            bR0 = bOK0 ? *reinterpret_cast<const float4*>(W + (size_t)(k0 + brow) * N + n0 + bcol)
                       : make_float4(0.f, 0.f, 0.f, 0.f);
            bR1 = bOK1 ? *reinterpret_cast<const float4*>(W + (size_t)(k0 + brow) * N + n0 + bcol + 4)
                       : make_float4(0.f, 0.f, 0.f, 0.f);
        }
#pragma unroll
        for (int kk = 0; kk < BK; kk++) {
            float ra[8], rb[8];
            *reinterpret_cast<float4*>(&ra[0]) = *reinterpret_cast<const float4*>(&As[buf][kk][ty * 8]);
            *reinterpret_cast<float4*>(&ra[4]) = *reinterpret_cast<const float4*>(&As[buf][kk][ty * 8 + 4]);
            *reinterpret_cast<float4*>(&rb[0]) = *reinterpret_cast<const float4*>(&Bs[buf][kk][tx * 8]);
            *reinterpret_cast<float4*>(&rb[4]) = *reinterpret_cast<const float4*>(&Bs[buf][kk][tx * 8 + 4]);
#pragma unroll
            for (int r = 0; r < 8; r++)
#pragma unroll
                for (int c = 0; c < 8; c++)
                    acc[r][c] += ra[r] * rb[c];
        }
        if (kt + 1 < nk) {
            const int nb = buf ^ 1;
            As[nb][acol + 0][arow] = aR.x;
            As[nb][acol + 1][arow] = aR.y;
            As[nb][acol + 2][arow] = aR.z;
            As[nb][acol + 3][arow] = aR.w;
            *reinterpret_cast<float4*>(&Bs[nb][brow][bcol]) = bR0;
            *reinterpret_cast<float4*>(&Bs[nb][brow][bcol + 4]) = bR1;
            __syncthreads();
        }
    }

#pragma unroll
    for (int r = 0; r < 8; r++) {
        int row = m0 + ty * 8 + r;
        if (row >= M) continue;
#pragma unroll
        for (int cc = 0; cc < 2; cc++) {
            int col = n0 + tx * 8 + cc * 4;
            if (col >= N) continue;
            float4 o;
            o.x = acc[r][cc * 4 + 0] + (bias ? bias[col + 0] : 0.f);
            o.y = acc[r][cc * 4 + 1] + (bias ? bias[col + 1] : 0.f);
            o.z = acc[r][cc * 4 + 2] + (bias ? bias[col + 2] : 0.f);
            o.w = acc[r][cc * 4 + 3] + (bias ? bias[col + 3] : 0.f);
            if (ACT == 1) {
                o.x = silu_f(o.x); o.y = silu_f(o.y);
                o.z = silu_f(o.z); o.w = silu_f(o.w);
            }
            *reinterpret_cast<float4*>(C + (size_t)row * N + col) = o;
        }
    }
}

// ---------------- final projection N=5 (warp per atom) ----------------
__global__ void out_kernel(const float* __restrict__ Wf3,
                           const float* __restrict__ bf3,
                           float* __restrict__ out) {
    int gw = (blockIdx.x * blockDim.x + threadIdx.x) >> 5;
    int lane = threadIdx.x & 31;
    if (gw >= NA) return;
    float acc[5] = {0.f, 0.f, 0.f, 0.f, 0.f};
    for (int k = lane; k < F; k += 32) {
        float h = g_t[gw * F + k];
#pragma unroll
        for (int o = 0; o < 5; o++) acc[o] += h * Wf3[k * 5 + o];
    }
#pragma unroll
    for (int o = 0; o < 5; o++) {
#pragma unroll
        for (int off = 16; off > 0; off >>= 1)
            acc[o] += __shfl_xor_sync(0xffffffffu, acc[o], off);
    }
    if (lane == 0) {
#pragma unroll
        for (int o = 0; o < 5; o++) out[gw * 5 + o] = acc[o] + bf3[o];
    }
}

// ---------------- host driver ----------------
static void* sym_addr_raw(const void* symbol) {
    void* p = nullptr;
    cudaGetSymbolAddress(&p, symbol);
    return p;
}

extern "C" void kernel_launch(void* const* d_in, const int* in_sizes, int n_in,
                              void* d_out, int out_size) {
    const float* xyz   = (const float*)d_in[0];
    const int*   z     = (const int*)d_in[1];
    const int*   nbrs  = (const int*)d_in[2];
    const float* embed = (const float*)d_in[3];
    const float* W1  = (const float*)d_in[4];
    const float* b1  = (const float*)d_in[5];
    const float* W2  = (const float*)d_in[6];
    const float* b2  = (const float*)d_in[7];
    const float* Wd  = (const float*)d_in[8];
    const float* bd  = (const float*)d_in[9];
    const float* U   = (const float*)d_in[10];
    const float* V   = (const float*)d_in[11];
    const float* Ws1 = (const float*)d_in[12];
    const float* bs1 = (const float*)d_in[13];
    const float* Ws2 = (const float*)d_in[14];
    const float* bs2 = (const float*)d_in[15];
    const float* Wr1 = (const float*)d_in[16];
    const float* br1 = (const float*)d_in[17];
    const float* Wr2 = (const float*)d_in[18];
    const float* br2 = (const float*)d_in[19];
    const float* Wf1 = (const float*)d_in[20];
    const float* bf1 = (const float*)d_in[21];
    const float* Wf2 = (const float*)d_in[22];
    const float* bf2 = (const float*)d_in[23];
    const float* Wf3 = (const float*)d_in[24];
    const float* bf3 = (const float*)d_in[25];
    float* out = (float*)d_out;

    float* s     = (float*)sym_addr_raw(g_s);
    float* va    = (float*)sym_addr_raw(g_va);
    float* vb    = (float*)sym_addr_raw(g_vb);
    float* t     = (float*)sym_addr_raw(g_t);
    float* phi   = (float*)sym_addr_raw(g_phi);
    float* uv    = (float*)sym_addr_raw(g_uv);
    float* vv    = (float*)sym_addr_raw(g_vv);
    float* split = (float*)sym_addr_raw(g_split);
    float* fea   = (float*)sym_addr_raw(g_fea);
    __nv_bfloat16* wh = (__nv_bfloat16*)sym_addr_raw(g_wh);
    __nv_bfloat16* wl = (__nv_bfloat16*)sym_addr_raw(g_wl);
    __nv_bfloat16* th = (__nv_bfloat16*)sym_addr_raw(g_th);
    __nv_bfloat16* tl = (__nv_bfloat16*)sym_addr_raw(g_tl);
    __nv_bfloat16* vh = (__nv_bfloat16*)sym_addr_raw(g_vh);
    __nv_bfloat16* vl = (__nv_bfloat16*)sym_addr_raw(g_vl);
    __nv_bfloat16* ch = (__nv_bfloat16*)sym_addr_raw(g_ch);
    __nv_bfloat16* cl = (__nv_bfloat16*)sym_addr_raw(g_cl);

    const int TPB = 256;
    dim3 w313_n128(1, 313);
    dim3 w313_n384(3, 313);
    dim3 w938_n128(1, 938);
    dim3 g313_n64(1, 313);

    wconv_all_kernel<<<(W_TOTAL + TPB - 1) / TPB, TPB>>>(W1, W2, U, V, Ws1, Ws2, Wr1, Wf1, Wf2);
    zero_cnt_kernel<<<(NA + 1 + TPB - 1) / TPB, TPB>>>();
    edge_geom_kernel<<<(NE + TPB - 1) / TPB, TPB>>>(xyz, nbrs);
    scan_kernel<<<1, 1024>>>();
    csr_fill_kernel<<<(NE + TPB - 1) / TPB, TPB>>>(nbrs);
    embed_init_kernel<<<(NA * F3 + TPB - 1) / TPB, TPB>>>(z, embed);

    for (int l = 0; l < NCONV; l++) {
        float* vin  = (l & 1) ? vb : va;
        float* vout = (l & 1) ? va : vb;

        // t(bf16 pair) = silu(s @ W1 + b1)
        wgemm_kernel<1, false, false, true><<<w313_n128, 256>>>(
            s, nullptr, nullptr, wh + OFF_W1 + l * F * F, wl + OFF_W1 + l * F * F,
            b1 + l * F, nullptr, th, tl, NA, F, F);
        // phi = t @ W2 + b2   (bf16 A)
        wgemm_kernel<0, false, true, false><<<w313_n384, 256>>>(
            nullptr, th, tl, wh + OFF_W2 + l * F * F3, wl + OFF_W2 + l * F * F3,
            b2 + l * F3, phi, nullptr, nullptr, NA, F3, F);

        edge_gather_kernel<<<NA, 128>>>(nbrs, Wd + l * NRBF * F3, bd + l * F3, vin, vout);

        // uv / vv = vout @ U / V   (bf16 A from gather epilogue)
        wgemm_kernel<0, true, true, false><<<w938_n128, 256>>>(
            nullptr, vh, vl, wh + OFF_U + l * F * F, wl + OFF_U + l * F * F,
            nullptr, uv, nullptr, nullptr, NA * 3, F, F);
        wgemm_kernel<0, true, true, false><<<w938_n128, 256>>>(
            nullptr, vh, vl, wh + OFF_V + l * F * F, wl + OFF_V + l * F * F,
            nullptr, vv, nullptr, nullptr, NA * 3, F, F);

        vnorm_cat_kernel<<<(NA * F + TPB - 1) / TPB, TPB>>>();

        // t(bf16 pair) = silu(cat @ Ws1 + bs1)   (bf16 A)
        wgemm_kernel<1, false, true, true><<<w313_n128, 256>>>(
            nullptr, ch, cl, wh + OFF_WS1 + l * 2 * F * F, wl + OFF_WS1 + l * 2 * F * F,
            bs1 + l * F, nullptr, th, tl, NA, F, 2 * F);
        // split = t @ Ws2 + bs2   (bf16 A)
        wgemm_kernel<0, false, true, false><<<w313_n384, 256>>>(
            nullptr, th, tl, wh + OFF_WS2 + l * F * F3, wl + OFF_WS2 + l * F * F3,
            bs2 + l * F3, split, nullptr, nullptr, NA, F3, F);

        update_kernel<<<(NA * F + TPB - 1) / TPB, TPB>>>(vout);
    }

    // readout (fp32 chain, unchanged)
    wgemm_kernel<1, false, false, false><<<w313_n128, 256>>>(
        s, nullptr, nullptr, wh + OFF_WR1, wl + OFF_WR1, br1, t, nullptr, nullptr, NA, F, F);
    sgemm64_kernel<0><<<g313_n64, 128>>>(t, Wr2, br2, fea, NA, 64, F);
    wgemm_kernel<1, false, false, false><<<w313_n128, 256>>>(
        fea, nullptr, nullptr, wh + OFF_WF1, wl + OFF_WF1, bf1, phi, nullptr, nullptr, NA, F, 64);
    wgemm_kernel<1, false, false, false><<<w313_n128, 256>>>(
        phi, nullptr, nullptr, wh + OFF_WF2, wl + OFF_WF2, bf2, t, nullptr, nullptr, NA, F, F);
    out_kernel<<<(NA * 32 + TPB - 1) / TPB, TPB>>>(Wf3, bf3, out);
}

// round 16
// speedup vs baseline: 1.0298x; 1.0298x over previous
#include <cuda_runtime.h>
#include <cuda_bf16.h>
#include <mma.h>
#include <math.h>

using namespace nvcuda;

#define NA 20000
#define NE 320000
#define F 128
#define F3 (3*F)
#define NRBF 20
#define NCONV 3
#define CUTOFF 5.0f
#define PI_F 3.14159265358979323846f

// weight-split buffer offsets (elements)
#define OFF_W1   0
#define OFF_W2   49152
#define OFF_U    196608
#define OFF_V    245760
#define OFF_WS1  294912
#define OFF_WS2  393216
#define OFF_WR1  540672
#define OFF_WF1  557056
#define OFF_WF2  565248
#define W_TOTAL  581632

// ---------------- scratch (device globals) ----------------
__device__ float g_s[NA * F];
__device__ float g_va[NA * F3];
__device__ float g_vb[NA * F3];
__device__ float g_t[NA * F];
__device__ float g_phi[NA * F3];
__device__ float g_uv[NA * F3];
__device__ float g_vv[NA * F3];
__device__ float g_cat[NA * 2 * F];
__device__ float g_split[NA * F3];
__device__ float g_unit[NE * 3];
__device__ float g_fcut[NE];
__device__ float g_rbf[NE * NRBF];
__device__ float g_fea[NA * 64];
__device__ __nv_bfloat16 g_wh[W_TOTAL];
__device__ __nv_bfloat16 g_wl[W_TOTAL];
__device__ int g_cnt[NA + 1];
__device__ int g_pos[NA];
__device__ int g_off[NA + 1];
__device__ int g_csr[NE];

__device__ __forceinline__ float silu_f(float x) { return x / (1.0f + expf(-x)); }

// ---------------- pre-split ALL weights to bf16 hi/lo (once per launch) ----
__global__ void wconv_all_kernel(const float* __restrict__ W1, const float* __restrict__ W2,
                                 const float* __restrict__ U,  const float* __restrict__ V,
                                 const float* __restrict__ Ws1, const float* __restrict__ Ws2,
                                 const float* __restrict__ Wr1, const float* __restrict__ Wf1,
                                 const float* __restrict__ Wf2) {
    int t = blockIdx.x * blockDim.x + threadIdx.x;
    if (t >= W_TOTAL) return;
    float x;
    if      (t < OFF_W2)  x = W1[t - OFF_W1];
    else if (t < OFF_U)   x = W2[t - OFF_W2];
    else if (t < OFF_V)   x = U[t - OFF_U];
    else if (t < OFF_WS1) x = V[t - OFF_V];
    else if (t < OFF_WS2) x = Ws1[t - OFF_WS1];
    else if (t < OFF_WR1) x = Ws2[t - OFF_WS2];
    else if (t < OFF_WF1) x = Wr1[t - OFF_WR1];
    else if (t < OFF_WF2) x = Wf1[t - OFF_WF1];
    else                  x = Wf2[t - OFF_WF2];
    __nv_bfloat16 h = __float2bfloat16(x);
    g_wh[t] = h;
    g_wl[t] = __float2bfloat16(x - __bfloat162float(h));
}

// ---------------- zero counters ----------------
__global__ void zero_cnt_kernel() {
    int t = blockIdx.x * blockDim.x + threadIdx.x;
    if (t <= NA) g_cnt[t] = 0;
    if (t < NA) g_pos[t] = 0;
}

// ---------------- edge geometry (Chebyshev rbf) + filtered degree count ----
__global__ void edge_geom_kernel(const float* __restrict__ xyz,
                                 const int* __restrict__ nbrs) {
    int e = blockIdx.x * blockDim.x + threadIdx.x;
    if (e >= NE) return;
    int i = nbrs[2 * e], j = nbrs[2 * e + 1];
    float dx = xyz[3 * j + 0] - xyz[3 * i + 0];
    float dy = xyz[3 * j + 1] - xyz[3 * i + 1];
    float dz = xyz[3 * j + 2] - xyz[3 * i + 2];
    float d = sqrtf(dx * dx + dy * dy + dz * dz + 1e-12f);
    float inv = 1.0f / d;
    g_unit[3 * e + 0] = dx * inv;
    g_unit[3 * e + 1] = dy * inv;
    g_unit[3 * e + 2] = dz * inv;
    float a = PI_F * d / CUTOFF;
    float s1, c1;
    sincosf(a, &s1, &c1);
    float fc = (d < CUTOFF) ? 0.5f * (c1 + 1.0f) : 0.0f;
    g_fcut[e] = fc;
    float two_c = 2.0f * c1;
    float sk_m1 = 0.0f;
    float sk = s1;
    g_rbf[e * NRBF + 0] = sk * inv;
#pragma unroll
    for (int k = 1; k < NRBF; k++) {
        float sk_p1 = two_c * sk - sk_m1;
        sk_m1 = sk;
        sk = sk_p1;
        g_rbf[e * NRBF + k] = sk * inv;
    }
    if (fc > 0.0f) atomicAdd(&g_cnt[i], 1);
}

// ---------------- exclusive scan over degrees ----------------
__global__ void scan_kernel() {
    __shared__ int part[1024];
    const int CH = (NA + 1023) / 1024;
    int t = threadIdx.x;
    int base = t * CH;
    int s = 0;
    for (int k = 0; k < CH; k++) {
        int idx = base + k;
        if (idx < NA) s += g_cnt[idx];
    }
    part[t] = s;
    __syncthreads();
    for (int off = 1; off < 1024; off <<= 1) {
        int v = (t >= off) ? part[t - off] : 0;
        __syncthreads();
        part[t] += v;
        __syncthreads();
    }
    int run = (t == 0) ? 0 : part[t - 1];
    for (int k = 0; k < CH; k++) {
        int idx = base + k;
        if (idx < NA) {
            g_off[idx] = run;
            run += g_cnt[idx];
        }
    }
    if (t == 0) g_off[NA] = part[1023];
}

// ---------------- fill CSR (filtered) ----------------
__global__ void csr_fill_kernel(const int* __restrict__ nbrs) {
    int e = blockIdx.x * blockDim.x + threadIdx.x;
    if (e >= NE) return;
    if (g_fcut[e] <= 0.0f) return;
    int i = nbrs[2 * e];
    int p = atomicAdd(&g_pos[i], 1);
    g_csr[g_off[i] + p] = e;
}

// ---------------- init: s = embed[z], va = 0 ----------------
__global__ void embed_init_kernel(const int* __restrict__ z,
                                  const float* __restrict__ embed) {
    int t = blockIdx.x * blockDim.x + threadIdx.x;
    if (t < NA * F) {
        int n = t / F, f = t % F;
        g_s[t] = embed[z[n] * F + f];
    }
    if (t < NA * F3) g_va[t] = 0.0f;
}

// ---------------- per-atom edge gather (R9 loop; phi bias b2 folded in) -----
__global__ void __launch_bounds__(128)
edge_gather_kernel(const int* __restrict__ nbrs,
                   const float* __restrict__ Wd,
                   const float* __restrict__ bd,
                   const float* __restrict__ b2,
                   const float* __restrict__ vin,
                   float* __restrict__ vout) {
    const int a = blockIdx.x;
    const int t = threadIdx.x;

    float wd0[NRBF], wd1[NRBF], wd2[NRBF];
#pragma unroll
    for (int k = 0; k < NRBF; k++) {
        wd0[k] = Wd[k * F3 + t];
        wd1[k] = Wd[k * F3 + F + t];
        wd2[k] = Wd[k * F3 + 2 * F + t];
    }
    const float b0 = bd[t], b1 = bd[F + t], b2r = bd[2 * F + t];
    const float pb0 = b2[t], pb1 = b2[F + t], pb2 = b2[2 * F + t];

    float acc_s = 0.f, acc_v0 = 0.f, acc_v1 = 0.f, acc_v2 = 0.f;

    const int beg = g_off[a], end = g_off[a + 1];
    int idx = beg;

    for (; idx + 2 <= end; idx += 2) {
        const int e0 = g_csr[idx];
        const int e1 = g_csr[idx + 1];
        const int j0 = __ldg(&nbrs[2 * e0 + 1]) * F3;
        const int j1 = __ldg(&nbrs[2 * e1 + 1]) * F3;
        const float fc0 = g_fcut[e0];
        const float fc1 = g_fcut[e1];
        const float u0x = g_unit[3 * e0 + 0], u0y = g_unit[3 * e0 + 1], u0z = g_unit[3 * e0 + 2];
        const float u1x = g_unit[3 * e1 + 0], u1y = g_unit[3 * e1 + 1], u1z = g_unit[3 * e1 + 2];

        const float p00 = g_phi[j0 + t] + pb0, p01 = g_phi[j0 + F + t] + pb1, p02 = g_phi[j0 + 2 * F + t] + pb2;
        const float p10 = g_phi[j1 + t] + pb0, p11 = g_phi[j1 + F + t] + pb1, p12 = g_phi[j1 + 2 * F + t] + pb2;
        const float va0 = vin[j0 + t],  va1 = vin[j0 + F + t],  va2 = vin[j0 + 2 * F + t];
        const float vb0 = vin[j1 + t],  vb1 = vin[j1 + F + t],  vb2 = vin[j1 + 2 * F + t];

        const float4* r0p = reinterpret_cast<const float4*>(&g_rbf[(size_t)e0 * NRBF]);
        const float4* r1p = reinterpret_cast<const float4*>(&g_rbf[(size_t)e1 * NRBF]);

        float w00 = b0, w01 = b1, w02 = b2r;
        float w10 = b0, w11 = b1, w12 = b2r;
#pragma unroll
        for (int q = 0; q < NRBF / 4; q++) {
            float4 r0 = r0p[q];
            float4 r1 = r1p[q];
            int k = 4 * q;
            w00 += r0.x * wd0[k] + r0.y * wd0[k + 1] + r0.z * wd0[k + 2] + r0.w * wd0[k + 3];
            w10 += r1.x * wd0[k] + r1.y * wd0[k + 1] + r1.z * wd0[k + 2] + r1.w * wd0[k + 3];
            w01 += r0.x * wd1[k] + r0.y * wd1[k + 1] + r0.z * wd1[k + 2] + r0.w * wd1[k + 3];
            w11 += r1.x * wd1[k] + r1.y * wd1[k + 1] + r1.z * wd1[k + 2] + r1.w * wd1[k + 3];
            w02 += r0.x * wd2[k] + r0.y * wd2[k + 1] + r0.z * wd2[k + 2] + r0.w * wd2[k + 3];
            w12 += r1.x * wd2[k] + r1.y * wd2[k + 1] + r1.z * wd2[k + 2] + r1.w * wd2[k + 3];
        }
        const float i00 = p00 * w00 * fc0, i01 = p01 * w01 * fc0, i02 = p02 * w02 * fc0;
        const float i10 = p10 * w10 * fc1, i11 = p11 * w11 * fc1, i12 = p12 * w12 * fc1;

        acc_s  += i01 + i11;
        acc_v0 += u0x * i02 + i00 * va0 + u1x * i12 + i10 * vb0;
        acc_v1 += u0y * i02 + i00 * va1 + u1y * i12 + i10 * vb1;
        acc_v2 += u0z * i02 + i00 * va2 + u1z * i12 + i10 * vb2;
    }

    if (idx < end) {
        const int e0 = g_csr[idx];
        const int j0 = __ldg(&nbrs[2 * e0 + 1]) * F3;
        const float fc0 = g_fcut[e0];
        const float u0x = g_unit[3 * e0 + 0], u0y = g_unit[3 * e0 + 1], u0z = g_unit[3 * e0 + 2];
        const float p00 = g_phi[j0 + t] + pb0, p01 = g_phi[j0 + F + t] + pb1, p02 = g_phi[j0 + 2 * F + t] + pb2;
        const float va0 = vin[j0 + t],  va1 = vin[j0 + F + t],  va2 = vin[j0 + 2 * F + t];
        const float4* r0p = reinterpret_cast<const float4*>(&g_rbf[(size_t)e0 * NRBF]);
        float w00 = b0, w01 = b1, w02 = b2r;
#pragma unroll
        for (int q = 0; q < NRBF / 4; q++) {
            float4 r0 = r0p[q];
            int k = 4 * q;
            w00 += r0.x * wd0[k] + r0.y * wd0[k + 1] + r0.z * wd0[k + 2] + r0.w * wd0[k + 3];
            w01 += r0.x * wd1[k] + r0.y * wd1[k + 1] + r0.z * wd1[k + 2] + r0.w * wd1[k + 3];
            w02 += r0.x * wd2[k] + r0.y * wd2[k + 1] + r0.z * wd2[k + 2] + r0.w * wd2[k + 3];
        }
        const float i00 = p00 * w00 * fc0, i01 = p01 * w01 * fc0, i02 = p02 * w02 * fc0;
        acc_s  += i01;
        acc_v0 += u0x * i02 + i00 * va0;
        acc_v1 += u0y * i02 + i00 * va1;
        acc_v2 += u0z * i02 + i00 * va2;
    }

    g_s[a * F + t] += acc_s;
    vout[a * F3 + t]         = vin[a * F3 + t]         + acc_v0;
    vout[a * F3 + F + t]     = vin[a * F3 + F + t]     + acc_v1;
    vout[a * F3 + 2 * F + t] = vin[a * F3 + 2 * F + t] + acc_v2;
}

// ---------------- vnorm + concat ----------------
__global__ void vnorm_cat_kernel() {
    int t = blockIdx.x * blockDim.x + threadIdx.x;
    if (t >= NA * F) return;
    int n = t / F, f = t % F;
    g_cat[n * 2 * F + f] = g_s[t];
    float a = g_vv[n * F3 + f];
    float b = g_vv[n * F3 + F + f];
    float c = g_vv[n * F3 + 2 * F + f];
    g_cat[n * 2 * F + F + f] = sqrtf(a * a + b * b + c * c + 1e-12f);
}

// ---------------- gated update (split bias bs2 folded in) ----------------
__global__ void update_kernel(float* __restrict__ v, const float* __restrict__ bs2) {
    int t = blockIdx.x * blockDim.x + threadIdx.x;
    if (t >= NA * F) return;
    int n = t / F, f = t % F;
    float avv = g_split[n * F3 + f]         + bs2[f];
    float asv = g_split[n * F3 + F + f]     + bs2[F + f];
    float ass = g_split[n * F3 + 2 * F + f] + bs2[2 * F + f];
    float dot = 0.0f;
#pragma unroll
    for (int d = 0; d < 3; d++) {
        float u = g_uv[n * F3 + d * F + f];
        float w = g_vv[n * F3 + d * F + f];
        dot += u * w;
        v[n * F3 + d * F + f] += u * avv;
    }
    g_s[t] += dot * asv + ass;
}

// ============== Tensor-core GEMM: BM=64, BN=128, BK=16, 8 warps =============
// A fp32 split in-kernel (packed bf16x2 stores); W pre-split bf16 hi/lo loaded
// as 16B vectors straight into smem (no cvt). fp32 accum.
#define WA_LD 24
#define WB_LD 136
#define WC_LD 20

template <int ACT, bool DIRECT>
__global__ void __launch_bounds__(256)
wgemm_kernel(const float* __restrict__ A,
             const __nv_bfloat16* __restrict__ Wh,
             const __nv_bfloat16* __restrict__ Wl,
             const float* __restrict__ bias, float* __restrict__ C,
             int M, int N, int K) {
    constexpr int BM = 64, BN = 128, BK = 16;
    __shared__ __nv_bfloat16 As_hi[BM][WA_LD];
    __shared__ __nv_bfloat16 As_lo[BM][WA_LD];
    __shared__ __nv_bfloat16 Bs_hi[BK][WB_LD];
    __shared__ __nv_bfloat16 Bs_lo[BK][WB_LD];
    __shared__ float cstage[8][16 * WC_LD];

    const int tid = threadIdx.x;
    const int wid = tid >> 5;
    const int m0 = blockIdx.y * BM, n0 = blockIdx.x * BN;

    const int arow = tid >> 2, ak = (tid & 3) << 2;
    const bool aOK = (m0 + arow < M);
    const int brow = tid >> 4, bcol = (tid & 15) << 3;

    wmma::fragment<wmma::accumulator, 16, 16, 16, float> c[2][2];
#pragma unroll
    for (int i = 0; i < 2; i++)
#pragma unroll
        for (int j = 0; j < 2; j++)
            wmma::fill_fragment(c[i][j], 0.0f);

    const int wm = (wid >> 2) * 32;
    const int wn = (wid & 3) * 32;

    const int nk = K / BK;
    for (int kt = 0; kt < nk; kt++) {
        const int k0 = kt * BK;
        {
            float buf[4];
            if (aOK) {
                *reinterpret_cast<float4*>(buf) =
                    *reinterpret_cast<const float4*>(A + (size_t)(m0 + arow) * K + k0 + ak);
            } else {
#pragma unroll
                for (int q = 0; q < 4; q++) buf[q] = 0.f;
            }
            __nv_bfloat16 h0 = __float2bfloat16(buf[0]);
            __nv_bfloat16 h1 = __float2bfloat16(buf[1]);
            __nv_bfloat16 h2 = __float2bfloat16(buf[2]);
            __nv_bfloat16 h3 = __float2bfloat16(buf[3]);
            __nv_bfloat162 hp0; hp0.x = h0; hp0.y = h1;
            __nv_bfloat162 hp1; hp1.x = h2; hp1.y = h3;
            __nv_bfloat162 lp0;
            lp0.x = __float2bfloat16(buf[0] - __bfloat162float(h0));
            lp0.y = __float2bfloat16(buf[1] - __bfloat162float(h1));
            __nv_bfloat162 lp1;
            lp1.x = __float2bfloat16(buf[2] - __bfloat162float(h2));
            lp1.y = __float2bfloat16(buf[3] - __bfloat162float(h3));
            *reinterpret_cast<__nv_bfloat162*>(&As_hi[arow][ak])     = hp0;
            *reinterpret_cast<__nv_bfloat162*>(&As_hi[arow][ak + 2]) = hp1;
            *reinterpret_cast<__nv_bfloat162*>(&As_lo[arow][ak])     = lp0;
            *reinterpret_cast<__nv_bfloat162*>(&As_lo[arow][ak + 2]) = lp1;
        }
        {
            const size_t woff = (size_t)(k0 + brow) * N + n0 + bcol;
            *reinterpret_cast<uint4*>(&Bs_hi[brow][bcol]) =
                *reinterpret_cast<const uint4*>(Wh + woff);
            *reinterpret_cast<uint4*>(&Bs_lo[brow][bcol]) =
                *reinterpret_cast<const uint4*>(Wl + woff);
        }
        __syncthreads();

        wmma::fragment<wmma::matrix_a, 16, 16, 16, __nv_bfloat16, wmma::row_major> ah[2], al[2];
        wmma::fragment<wmma::matrix_b, 16, 16, 16, __nv_bfloat16, wmma::row_major> bh[2], bl[2];
#pragma unroll
        for (int i = 0; i < 2; i++) {
            wmma::load_matrix_sync(ah[i], &As_hi[wm + i * 16][0], WA_LD);
            wmma::load_matrix_sync(al[i], &As_lo[wm + i * 16][0], WA_LD);
        }
#pragma unroll
        for (int j = 0; j < 2; j++) {
            wmma::load_matrix_sync(bh[j], &Bs_hi[0][wn + j * 16], WB_LD);
            wmma::load_matrix_sync(bl[j], &Bs_lo[0][wn + j * 16], WB_LD);
        }
#pragma unroll
        for (int i = 0; i < 2; i++)
#pragma unroll
            for (int j = 0; j < 2; j++) {
                wmma::mma_sync(c[i][j], ah[i], bh[j], c[i][j]);
                wmma::mma_sync(c[i][j], ah[i], bl[j], c[i][j]);
                wmma::mma_sync(c[i][j], al[i], bh[j], c[i][j]);
            }
        __syncthreads();
    }

    const int lane = tid & 31;
#pragma unroll
    for (int i = 0; i < 2; i++) {
        const int grow0 = m0 + wm + i * 16;
#pragma unroll
        for (int j = 0; j < 2; j++) {
            const int gcol0 = n0 + wn + j * 16;
            if (DIRECT && grow0 + 16 <= M) {
                wmma::store_matrix_sync(C + (size_t)grow0 * N + gcol0, c[i][j], N,
                                        wmma::mem_row_major);
            } else {
                wmma::store_matrix_sync(&cstage[wid][0], c[i][j], WC_LD, wmma::mem_row_major);
                __syncwarp();
#pragma unroll
                for (int e = 0; e < 8; e++) {
                    int el = e * 32 + lane;
                    int r = el >> 4, cc = el & 15;
                    int grow = grow0 + r;
                    if (grow < M) {
                        int gcol = gcol0 + cc;
                        float x = cstage[wid][r * WC_LD + cc] + (bias ? bias[gcol] : 0.f);
                        if (ACT == 1) x = silu_f(x);
                        C[(size_t)grow * N + gcol] = x;
                    }
                }
                __syncwarp();
            }
        }
    }
}

// ---------------- fp32 SGEMM 64x128 (readout N=64 only) ----------------
template <int ACT>
__global__ void __launch_bounds__(128)
sgemm64_kernel(const float* __restrict__ A, const float* __restrict__ W,
               const float* __restrict__ bias, float* __restrict__ C,
               int M, int N, int K) {
    constexpr int BM = 64, BN = 128, BK = 8;
    __shared__ float As[2][BK][BM];
    __shared__ float Bs[2][BK][BN];
    const int tid = threadIdx.x;
    const int m0 = blockIdx.y * BM, n0 = blockIdx.x * BN;
    const int arow = tid >> 1, acol = (tid & 1) << 2;
    const int brow = tid >> 4, bcol = (tid & 15) << 3;
    const int tx = tid & 15, ty = tid >> 4;

    float acc[8][8] = {};
    float4 aR, bR0, bR1;
    const int gmA = m0 + arow;
    const bool aOK = (gmA < M);
    const bool bOK0 = (n0 + bcol < N);
    const bool bOK1 = (n0 + bcol + 4 < N);

    aR = aOK ? *reinterpret_cast<const float4*>(A + (size_t)gmA * K + acol)
             : make_float4(0.f, 0.f, 0.f, 0.f);
    bR0 = bOK0 ? *reinterpret_cast<const float4*>(W + (size_t)brow * N + n0 + bcol)
               : make_float4(0.f, 0.f, 0.f, 0.f);
    bR1 = bOK1 ? *reinterpret_cast<const float4*>(W + (size_t)brow * N + n0 + bcol + 4)
               : make_float4(0.f, 0.f, 0.f, 0.f);
    As[0][acol + 0][arow] = aR.x;
    As[0][acol + 1][arow] = aR.y;
    As[0][acol + 2][arow] = aR.z;
    As[0][acol + 3][arow] = aR.w;
    *reinterpret_cast<float4*>(&Bs[0][brow][bcol]) = bR0;
    *reinterpret_cast<float4*>(&Bs[0][brow][bcol + 4]) = bR1;
    __syncthreads();

    const int nk = K / BK;
    for (int kt = 0; kt < nk; kt++) {
        const int buf = kt & 1;
        if (kt + 1 < nk) {
            int k0 = (kt + 1) * BK;
            aR = aOK ? *reinterpret_cast<const float4*>(A + (size_t)gmA * K + k0 + acol)
                     : make_float4(0.f, 0.f, 0.f, 0.f);
            bR0 = bOK0 ? *reinterpret_cast<const float4*>(W + (size_t)(k0 + brow) * N + n0 + bcol)
                       : make_float4(0.f, 0.f, 0.f, 0.f);
            bR1 = bOK1 ? *reinterpret_cast<const float4*>(W + (size_t)(k0 + brow) * N + n0 + bcol + 4)
                       : make_float4(0.f, 0.f, 0.f, 0.f);
        }
#pragma unroll
        for (int kk = 0; kk < BK; kk++) {
            float ra[8], rb[8];
            *reinterpret_cast<float4*>(&ra[0]) = *reinterpret_cast<const float4*>(&As[buf][kk][ty * 8]);
            *reinterpret_cast<float4*>(&ra[4]) = *reinterpret_cast<const float4*>(&As[buf][kk][ty * 8 + 4]);
            *reinterpret_cast<float4*>(&rb[0]) = *reinterpret_cast<const float4*>(&Bs[buf][kk][tx * 8]);
            *reinterpret_cast<float4*>(&rb[4]) = *reinterpret_cast<const float4*>(&Bs[buf][kk][tx * 8 + 4]);
#pragma unroll
            for (int r = 0; r < 8; r++)
#pragma unroll
                for (int c = 0; c < 8; c++)
                    acc[r][c] += ra[r] * rb[c];
        }
        if (kt + 1 < nk) {
            const int nb = buf ^ 1;
            As[nb][acol + 0][arow] = aR.x;
            As[nb][acol + 1][arow] = aR.y;
            As[nb][acol + 2][arow] = aR.z;
            As[nb][acol + 3][arow] = aR.w;
            *reinterpret_cast<float4*>(&Bs[nb][brow][bcol]) = bR0;
            *reinterpret_cast<float4*>(&Bs[nb][brow][bcol + 4]) = bR1;
            __syncthreads();
        }
    }

#pragma unroll
    for (int r = 0; r < 8; r++) {
        int row = m0 + ty * 8 + r;
        if (row >= M) continue;
#pragma unroll
        for (int cc = 0; cc < 2; cc++) {
            int col = n0 + tx * 8 + cc * 4;
            if (col >= N) continue;
            float4 o;
            o.x = acc[r][cc * 4 + 0] + (bias ? bias[col + 0] : 0.f);
            o.y = acc[r][cc * 4 + 1] + (bias ? bias[col + 1] : 0.f);
            o.z = acc[r][cc * 4 + 2] + (bias ? bias[col + 2] : 0.f);
            o.w = acc[r][cc * 4 + 3] + (bias ? bias[col + 3] : 0.f);
            if (ACT == 1) {
                o.x = silu_f(o.x); o.y = silu_f(o.y);
                o.z = silu_f(o.z); o.w = silu_f(o.w);
            }
            *reinterpret_cast<float4*>(C + (size_t)row * N + col) = o;
        }
    }
}

// ---------------- final projection N=5 (warp per atom) ----------------
__global__ void out_kernel(const float* __restrict__ Wf3,
                           const float* __restrict__ bf3,
                           float* __restrict__ out) {
    int gw = (blockIdx.x * blockDim.x + threadIdx.x) >> 5;
    int lane = threadIdx.x & 31;
    if (gw >= NA) return;
    float acc[5] = {0.f, 0.f, 0.f, 0.f, 0.f};
    for (int k = lane; k < F; k += 32) {
        float h = g_t[gw * F + k];
#pragma unroll
        for (int o = 0; o < 5; o++) acc[o] += h * Wf3[k * 5 + o];
    }
#pragma unroll
    for (int o = 0; o < 5; o++) {
#pragma unroll
        for (int off = 16; off > 0; off >>= 1)
            acc[o] += __shfl_xor_sync(0xffffffffu, acc[o], off);
    }
    if (lane == 0) {
#pragma unroll
        for (int o = 0; o < 5; o++) out[gw * 5 + o] = acc[o] + bf3[o];
    }
}

// ---------------- host driver ----------------
static void* sym_addr_raw(const void* symbol) {
    void* p = nullptr;
    cudaGetSymbolAddress(&p, symbol);
    return p;
}

extern "C" void kernel_launch(void* const* d_in, const int* in_sizes, int n_in,
                              void* d_out, int out_size) {
    const float* xyz   = (const float*)d_in[0];
    const int*   z     = (const int*)d_in[1];
    const int*   nbrs  = (const int*)d_in[2];
    const float* embed = (const float*)d_in[3];
    const float* W1  = (const float*)d_in[4];
    const float* b1  = (const float*)d_in[5];
    const float* W2  = (const float*)d_in[6];
    const float* b2  = (const float*)d_in[7];
    const float* Wd  = (const float*)d_in[8];
    const float* bd  = (const float*)d_in[9];
    const float* U   = (const float*)d_in[10];
    const float* V   = (const float*)d_in[11];
    const float* Ws1 = (const float*)d_in[12];
    const float* bs1 = (const float*)d_in[13];
    const float* Ws2 = (const float*)d_in[14];
    const float* bs2 = (const float*)d_in[15];
    const float* Wr1 = (const float*)d_in[16];
    const float* br1 = (const float*)d_in[17];
    const float* Wr2 = (const float*)d_in[18];
    const float* br2 = (const float*)d_in[19];
    const float* Wf1 = (const float*)d_in[20];
    const float* bf1 = (const float*)d_in[21];
    const float* Wf2 = (const float*)d_in[22];
    const float* bf2 = (const float*)d_in[23];
    const float* Wf3 = (const float*)d_in[24];
    const float* bf3 = (const float*)d_in[25];
    float* out = (float*)d_out;

    float* s     = (float*)sym_addr_raw(g_s);
    float* va    = (float*)sym_addr_raw(g_va);
    float* vb    = (float*)sym_addr_raw(g_vb);
    float* t     = (float*)sym_addr_raw(g_t);
    float* phi   = (float*)sym_addr_raw(g_phi);
    float* uv    = (float*)sym_addr_raw(g_uv);
    float* vv    = (float*)sym_addr_raw(g_vv);
    float* cat   = (float*)sym_addr_raw(g_cat);
    float* split = (float*)sym_addr_raw(g_split);
    float* fea   = (float*)sym_addr_raw(g_fea);
    __nv_bfloat16* wh = (__nv_bfloat16*)sym_addr_raw(g_wh);
    __nv_bfloat16* wl = (__nv_bfloat16*)sym_addr_raw(g_wl);

    const int TPB = 256;
    dim3 w313_n128(1, 313);
    dim3 w313_n384(3, 313);
    dim3 w938_n128(1, 938);
    dim3 g313_n64(1, 313);

    wconv_all_kernel<<<(W_TOTAL + TPB - 1) / TPB, TPB>>>(W1, W2, U, V, Ws1, Ws2, Wr1, Wf1, Wf2);
    zero_cnt_kernel<<<(NA + 1 + TPB - 1) / TPB, TPB>>>();
    edge_geom_kernel<<<(NE + TPB - 1) / TPB, TPB>>>(xyz, nbrs);
    scan_kernel<<<1, 1024>>>();
    csr_fill_kernel<<<(NE + TPB - 1) / TPB, TPB>>>(nbrs);
    embed_init_kernel<<<(NA * F3 + TPB - 1) / TPB, TPB>>>(z, embed);

    for (int l = 0; l < NCONV; l++) {
        float* vin  = (l & 1) ? vb : va;
        float* vout = (l & 1) ? va : vb;

        wgemm_kernel<1, false><<<w313_n128, 256>>>(s, wh + OFF_W1 + l * F * F, wl + OFF_W1 + l * F * F,
                                                   b1 + l * F, t, NA, F, F);
        // phi = t @ W2 (bias b2 folded into gather) -> DIRECT epilogue
        wgemm_kernel<0, true><<<w313_n384, 256>>>(t, wh + OFF_W2 + l * F * F3, wl + OFF_W2 + l * F * F3,
                                                  nullptr, phi, NA, F3, F);

        edge_gather_kernel<<<NA, 128>>>(nbrs, Wd + l * NRBF * F3, bd + l * F3, b2 + l * F3, vin, vout);

        wgemm_kernel<0, true><<<w938_n128, 256>>>(vout, wh + OFF_U + l * F * F, wl + OFF_U + l * F * F,
                                                  nullptr, uv, NA * 3, F, F);
        wgemm_kernel<0, true><<<w938_n128, 256>>>(vout, wh + OFF_V + l * F * F, wl + OFF_V + l * F * F,
                                                  nullptr, vv, NA * 3, F, F);

        vnorm_cat_kernel<<<(NA * F + TPB - 1) / TPB, TPB>>>();

        wgemm_kernel<1, false><<<w313_n128, 256>>>(cat, wh + OFF_WS1 + l * 2 * F * F, wl + OFF_WS1 + l * 2 * F * F,
                                                   bs1 + l * F, t, NA, F, 2 * F);
        // split = t @ Ws2 (bias bs2 folded into update) -> DIRECT epilogue
        wgemm_kernel<0, true><<<w313_n384, 256>>>(t, wh + OFF_WS2 + l * F * F3, wl + OFF_WS2 + l * F * F3,
                                                  nullptr, split, NA, F3, F);

        update_kernel<<<(NA * F + TPB - 1) / TPB, TPB>>>(vout, bs2 + l * F3);
    }

    wgemm_kernel<1, false><<<w313_n128, 256>>>(s, wh + OFF_WR1, wl + OFF_WR1, br1, t, NA, F, F);
    sgemm64_kernel<0><<<g313_n64, 128>>>(t, Wr2, br2, fea, NA, 64, F);
    wgemm_kernel<1, false><<<w313_n128, 256>>>(fea, wh + OFF_WF1, wl + OFF_WF1, bf1, phi, NA, F, 64);
    wgemm_kernel<1, false><<<w313_n128, 256>>>(phi, wh + OFF_WF2, wl + OFF_WF2, bf2, t, NA, F, F);
    out_kernel<<<(NA * 32 + TPB - 1) / TPB, TPB>>>(Wf3, bf3, out);
}

// round 17
// speedup vs baseline: 1.0450x; 1.0148x over previous
#include <cuda_runtime.h>
#include <cuda_bf16.h>
#include <mma.h>
#include <math.h>

using namespace nvcuda;

#define NA 20000
#define NE 320000
#define F 128
#define F3 (3*F)
#define NRBF 20
#define NCONV 3
#define CUTOFF 5.0f
#define PI_F 3.14159265358979323846f

// weight-split buffer offsets (elements)
#define OFF_W1   0
#define OFF_W2   49152
#define OFF_U    196608
#define OFF_V    245760
#define OFF_WS1  294912
#define OFF_WS2  393216
#define OFF_WR1  540672
#define OFF_WF1  557056
#define OFF_WF2  565248
#define W_TOTAL  581632

// ---------------- scratch (device globals) ----------------
__device__ float g_s[NA * F];
__device__ float g_va[NA * F3];
__device__ float g_vb[NA * F3];
__device__ float g_t[NA * F];
__device__ float g_phi[NA * F3];
__device__ float g_uv[NA * F3];
__device__ float g_vv[NA * F3];
__device__ float g_cat[NA * 2 * F];
__device__ float g_split[NA * F3];
__device__ float g_unit[NE * 3];
__device__ float g_fcut[NE];
__device__ float g_rbf[NE * NRBF];
__device__ float g_fea[NA * 64];
__device__ __nv_bfloat16 g_wh[W_TOTAL];
__device__ __nv_bfloat16 g_wl[W_TOTAL];
__device__ int g_cnt[NA + 1];
__device__ int g_pos[NA];
__device__ int g_off[NA + 1];
__device__ int g_csr[NE];

__device__ __forceinline__ float silu_f(float x) { return x / (1.0f + expf(-x)); }

// ---------------- pre-split ALL weights to bf16 hi/lo (once per launch) ----
__global__ void wconv_all_kernel(const float* __restrict__ W1, const float* __restrict__ W2,
                                 const float* __restrict__ U,  const float* __restrict__ V,
                                 const float* __restrict__ Ws1, const float* __restrict__ Ws2,
                                 const float* __restrict__ Wr1, const float* __restrict__ Wf1,
                                 const float* __restrict__ Wf2) {
    int t = blockIdx.x * blockDim.x + threadIdx.x;
    if (t >= W_TOTAL) return;
    float x;
    if      (t < OFF_W2)  x = W1[t - OFF_W1];
    else if (t < OFF_U)   x = W2[t - OFF_W2];
    else if (t < OFF_V)   x = U[t - OFF_U];
    else if (t < OFF_WS1) x = V[t - OFF_V];
    else if (t < OFF_WS2) x = Ws1[t - OFF_WS1];
    else if (t < OFF_WR1) x = Ws2[t - OFF_WS2];
    else if (t < OFF_WF1) x = Wr1[t - OFF_WR1];
    else if (t < OFF_WF2) x = Wf1[t - OFF_WF1];
    else                  x = Wf2[t - OFF_WF2];
    __nv_bfloat16 h = __float2bfloat16(x);
    g_wh[t] = h;
    g_wl[t] = __float2bfloat16(x - __bfloat162float(h));
}

// ---------------- zero counters ----------------
__global__ void zero_cnt_kernel() {
    int t = blockIdx.x * blockDim.x + threadIdx.x;
    if (t <= NA) g_cnt[t] = 0;
    if (t < NA) g_pos[t] = 0;
}

// ---------------- edge geometry (Chebyshev rbf) + filtered degree count ----
__global__ void edge_geom_kernel(const float* __restrict__ xyz,
                                 const int* __restrict__ nbrs) {
    int e = blockIdx.x * blockDim.x + threadIdx.x;
    if (e >= NE) return;
    int i = nbrs[2 * e], j = nbrs[2 * e + 1];
    float dx = xyz[3 * j + 0] - xyz[3 * i + 0];
    float dy = xyz[3 * j + 1] - xyz[3 * i + 1];
    float dz = xyz[3 * j + 2] - xyz[3 * i + 2];
    float d = sqrtf(dx * dx + dy * dy + dz * dz + 1e-12f);
    float inv = 1.0f / d;
    g_unit[3 * e + 0] = dx * inv;
    g_unit[3 * e + 1] = dy * inv;
    g_unit[3 * e + 2] = dz * inv;
    float a = PI_F * d / CUTOFF;
    float s1, c1;
    sincosf(a, &s1, &c1);
    float fc = (d < CUTOFF) ? 0.5f * (c1 + 1.0f) : 0.0f;
    g_fcut[e] = fc;
    float two_c = 2.0f * c1;
    float sk_m1 = 0.0f;
    float sk = s1;
    g_rbf[e * NRBF + 0] = sk * inv;
#pragma unroll
    for (int k = 1; k < NRBF; k++) {
        float sk_p1 = two_c * sk - sk_m1;
        sk_m1 = sk;
        sk = sk_p1;
        g_rbf[e * NRBF + k] = sk * inv;
    }
    if (fc > 0.0f) atomicAdd(&g_cnt[i], 1);
}

// ---------------- exclusive scan over degrees ----------------
__global__ void scan_kernel() {
    __shared__ int part[1024];
    const int CH = (NA + 1023) / 1024;
    int t = threadIdx.x;
    int base = t * CH;
    int s = 0;
    for (int k = 0; k < CH; k++) {
        int idx = base + k;
        if (idx < NA) s += g_cnt[idx];
    }
    part[t] = s;
    __syncthreads();
    for (int off = 1; off < 1024; off <<= 1) {
        int v = (t >= off) ? part[t - off] : 0;
        __syncthreads();
        part[t] += v;
        __syncthreads();
    }
    int run = (t == 0) ? 0 : part[t - 1];
    for (int k = 0; k < CH; k++) {
        int idx = base + k;
        if (idx < NA) {
            g_off[idx] = run;
            run += g_cnt[idx];
        }
    }
    if (t == 0) g_off[NA] = part[1023];
}

// ---------------- fill CSR (filtered) ----------------
__global__ void csr_fill_kernel(const int* __restrict__ nbrs) {
    int e = blockIdx.x * blockDim.x + threadIdx.x;
    if (e >= NE) return;
    if (g_fcut[e] <= 0.0f) return;
    int i = nbrs[2 * e];
    int p = atomicAdd(&g_pos[i], 1);
    g_csr[g_off[i] + p] = e;
}

// ---------------- init: s = embed[z], va = 0 ----------------
__global__ void embed_init_kernel(const int* __restrict__ z,
                                  const float* __restrict__ embed) {
    int t = blockIdx.x * blockDim.x + threadIdx.x;
    if (t < NA * F) {
        int n = t / F, f = t % F;
        g_s[t] = embed[z[n] * F + f];
    }
    if (t < NA * F3) g_va[t] = 0.0f;
}

// ---------------- per-atom edge gather, 4-edge unroll (deeper MLP) ---------
__global__ void __launch_bounds__(128)
edge_gather_kernel(const int* __restrict__ nbrs,
                   const float* __restrict__ Wd,
                   const float* __restrict__ bd,
                   const float* __restrict__ vin,
                   float* __restrict__ vout) {
    const int a = blockIdx.x;
    const int t = threadIdx.x;

    float wd0[NRBF], wd1[NRBF], wd2[NRBF];
#pragma unroll
    for (int k = 0; k < NRBF; k++) {
        wd0[k] = Wd[k * F3 + t];
        wd1[k] = Wd[k * F3 + F + t];
        wd2[k] = Wd[k * F3 + 2 * F + t];
    }
    const float b0 = bd[t], b1 = bd[F + t], b2 = bd[2 * F + t];

    float acc_s = 0.f, acc_v0 = 0.f, acc_v1 = 0.f, acc_v2 = 0.f;

    const int beg = g_off[a], end = g_off[a + 1];
    int idx = beg;

    // ---- 4-edge unrolled main loop: all loads issued before dependent FMAs
    for (; idx + 4 <= end; idx += 4) {
        const int e0 = g_csr[idx];
        const int e1 = g_csr[idx + 1];
        const int e2 = g_csr[idx + 2];
        const int e3 = g_csr[idx + 3];
        const int j0 = __ldg(&nbrs[2 * e0 + 1]) * F3;
        const int j1 = __ldg(&nbrs[2 * e1 + 1]) * F3;
        const int j2 = __ldg(&nbrs[2 * e2 + 1]) * F3;
        const int j3 = __ldg(&nbrs[2 * e3 + 1]) * F3;
        const float fc0 = g_fcut[e0], fc1 = g_fcut[e1];
        const float fc2 = g_fcut[e2], fc3 = g_fcut[e3];
        const float u0x = g_unit[3 * e0 + 0], u0y = g_unit[3 * e0 + 1], u0z = g_unit[3 * e0 + 2];
        const float u1x = g_unit[3 * e1 + 0], u1y = g_unit[3 * e1 + 1], u1z = g_unit[3 * e1 + 2];
        const float u2x = g_unit[3 * e2 + 0], u2y = g_unit[3 * e2 + 1], u2z = g_unit[3 * e2 + 2];
        const float u3x = g_unit[3 * e3 + 0], u3y = g_unit[3 * e3 + 1], u3z = g_unit[3 * e3 + 2];

        const float p00 = g_phi[j0 + t], p01 = g_phi[j0 + F + t], p02 = g_phi[j0 + 2 * F + t];
        const float p10 = g_phi[j1 + t], p11 = g_phi[j1 + F + t], p12 = g_phi[j1 + 2 * F + t];
        const float p20 = g_phi[j2 + t], p21 = g_phi[j2 + F + t], p22 = g_phi[j2 + 2 * F + t];
        const float p30 = g_phi[j3 + t], p31 = g_phi[j3 + F + t], p32 = g_phi[j3 + 2 * F + t];
        const float va0 = vin[j0 + t], va1 = vin[j0 + F + t], va2 = vin[j0 + 2 * F + t];
        const float vb0 = vin[j1 + t], vb1 = vin[j1 + F + t], vb2 = vin[j1 + 2 * F + t];
        const float vc0 = vin[j2 + t], vc1 = vin[j2 + F + t], vc2 = vin[j2 + 2 * F + t];
        const float vd0 = vin[j3 + t], vd1 = vin[j3 + F + t], vd2 = vin[j3 + 2 * F + t];

        const float4* r0p = reinterpret_cast<const float4*>(&g_rbf[(size_t)e0 * NRBF]);
        const float4* r1p = reinterpret_cast<const float4*>(&g_rbf[(size_t)e1 * NRBF]);
        const float4* r2p = reinterpret_cast<const float4*>(&g_rbf[(size_t)e2 * NRBF]);
        const float4* r3p = reinterpret_cast<const float4*>(&g_rbf[(size_t)e3 * NRBF]);

        float w00 = b0, w01 = b1, w02 = b2;
        float w10 = b0, w11 = b1, w12 = b2;
        float w20 = b0, w21 = b1, w22 = b2;
        float w30 = b0, w31 = b1, w32 = b2;
#pragma unroll
        for (int q = 0; q < NRBF / 4; q++) {
            float4 r0 = r0p[q];
            float4 r1 = r1p[q];
            float4 r2 = r2p[q];
            float4 r3 = r3p[q];
            int k = 4 * q;
            w00 += r0.x * wd0[k] + r0.y * wd0[k + 1] + r0.z * wd0[k + 2] + r0.w * wd0[k + 3];
            w10 += r1.x * wd0[k] + r1.y * wd0[k + 1] + r1.z * wd0[k + 2] + r1.w * wd0[k + 3];
            w20 += r2.x * wd0[k] + r2.y * wd0[k + 1] + r2.z * wd0[k + 2] + r2.w * wd0[k + 3];
            w30 += r3.x * wd0[k] + r3.y * wd0[k + 1] + r3.z * wd0[k + 2] + r3.w * wd0[k + 3];
            w01 += r0.x * wd1[k] + r0.y * wd1[k + 1] + r0.z * wd1[k + 2] + r0.w * wd1[k + 3];
            w11 += r1.x * wd1[k] + r1.y * wd1[k + 1] + r1.z * wd1[k + 2] + r1.w * wd1[k + 3];
            w21 += r2.x * wd1[k] + r2.y * wd1[k + 1] + r2.z * wd1[k + 2] + r2.w * wd1[k + 3];
            w31 += r3.x * wd1[k] + r3.y * wd1[k + 1] + r3.z * wd1[k + 2] + r3.w * wd1[k + 3];
            w02 += r0.x * wd2[k] + r0.y * wd2[k + 1] + r0.z * wd2[k + 2] + r0.w * wd2[k + 3];
            w12 += r1.x * wd2[k] + r1.y * wd2[k + 1] + r1.z * wd2[k + 2] + r1.w * wd2[k + 3];
            w22 += r2.x * wd2[k] + r2.y * wd2[k + 1] + r2.z * wd2[k + 2] + r2.w * wd2[k + 3];
            w32 += r3.x * wd2[k] + r3.y * wd2[k + 1] + r3.z * wd2[k + 2] + r3.w * wd2[k + 3];
        }
        const float i00 = p00 * w00 * fc0, i01 = p01 * w01 * fc0, i02 = p02 * w02 * fc0;
        const float i10 = p10 * w10 * fc1, i11 = p11 * w11 * fc1, i12 = p12 * w12 * fc1;
        const float i20 = p20 * w20 * fc2, i21 = p21 * w21 * fc2, i22 = p22 * w22 * fc2;
        const float i30 = p30 * w30 * fc3, i31 = p31 * w31 * fc3, i32 = p32 * w32 * fc3;

        acc_s  += (i01 + i11) + (i21 + i31);
        acc_v0 += (u0x * i02 + i00 * va0 + u1x * i12 + i10 * vb0)
                + (u2x * i22 + i20 * vc0 + u3x * i32 + i30 * vd0);
        acc_v1 += (u0y * i02 + i00 * va1 + u1y * i12 + i10 * vb1)
                + (u2y * i22 + i20 * vc1 + u3y * i32 + i30 * vd1);
        acc_v2 += (u0z * i02 + i00 * va2 + u1z * i12 + i10 * vb2)
                + (u2z * i22 + i20 * vc2 + u3z * i32 + i30 * vd2);
    }

    // ---- 2-edge remainder (identical to champion loop body)
    for (; idx + 2 <= end; idx += 2) {
        const int e0 = g_csr[idx];
        const int e1 = g_csr[idx + 1];
        const int j0 = __ldg(&nbrs[2 * e0 + 1]) * F3;
        const int j1 = __ldg(&nbrs[2 * e1 + 1]) * F3;
        const float fc0 = g_fcut[e0];
        const float fc1 = g_fcut[e1];
        const float u0x = g_unit[3 * e0 + 0], u0y = g_unit[3 * e0 + 1], u0z = g_unit[3 * e0 + 2];
        const float u1x = g_unit[3 * e1 + 0], u1y = g_unit[3 * e1 + 1], u1z = g_unit[3 * e1 + 2];

        const float p00 = g_phi[j0 + t], p01 = g_phi[j0 + F + t], p02 = g_phi[j0 + 2 * F + t];
        const float p10 = g_phi[j1 + t], p11 = g_phi[j1 + F + t], p12 = g_phi[j1 + 2 * F + t];
        const float va0 = vin[j0 + t],  va1 = vin[j0 + F + t],  va2 = vin[j0 + 2 * F + t];
        const float vb0 = vin[j1 + t],  vb1 = vin[j1 + F + t],  vb2 = vin[j1 + 2 * F + t];

        const float4* r0p = reinterpret_cast<const float4*>(&g_rbf[(size_t)e0 * NRBF]);
        const float4* r1p = reinterpret_cast<const float4*>(&g_rbf[(size_t)e1 * NRBF]);

        float w00 = b0, w01 = b1, w02 = b2;
        float w10 = b0, w11 = b1, w12 = b2;
#pragma unroll
        for (int q = 0; q < NRBF / 4; q++) {
            float4 r0 = r0p[q];
            float4 r1 = r1p[q];
            int k = 4 * q;
            w00 += r0.x * wd0[k] + r0.y * wd0[k + 1] + r0.z * wd0[k + 2] + r0.w * wd0[k + 3];
            w10 += r1.x * wd0[k] + r1.y * wd0[k + 1] + r1.z * wd0[k + 2] + r1.w * wd0[k + 3];
            w01 += r0.x * wd1[k] + r0.y * wd1[k + 1] + r0.z * wd1[k + 2] + r0.w * wd1[k + 3];
            w11 += r1.x * wd1[k] + r1.y * wd1[k + 1] + r1.z * wd1[k + 2] + r1.w * wd1[k + 3];
            w02 += r0.x * wd2[k] + r0.y * wd2[k + 1] + r0.z * wd2[k + 2] + r0.w * wd2[k + 3];
            w12 += r1.x * wd2[k] + r1.y * wd2[k + 1] + r1.z * wd2[k + 2] + r1.w * wd2[k + 3];
        }
        const float i00 = p00 * w00 * fc0, i01 = p01 * w01 * fc0, i02 = p02 * w02 * fc0;
        const float i10 = p10 * w10 * fc1, i11 = p11 * w11 * fc1, i12 = p12 * w12 * fc1;

        acc_s  += i01 + i11;
        acc_v0 += u0x * i02 + i00 * va0 + u1x * i12 + i10 * vb0;
        acc_v1 += u0y * i02 + i00 * va1 + u1y * i12 + i10 * vb1;
        acc_v2 += u0z * i02 + i00 * va2 + u1z * i12 + i10 * vb2;
    }

    if (idx < end) {
        const int e0 = g_csr[idx];
        const int j0 = __ldg(&nbrs[2 * e0 + 1]) * F3;
        const float fc0 = g_fcut[e0];
        const float u0x = g_unit[3 * e0 + 0], u0y = g_unit[3 * e0 + 1], u0z = g_unit[3 * e0 + 2];
        const float p00 = g_phi[j0 + t], p01 = g_phi[j0 + F + t], p02 = g_phi[j0 + 2 * F + t];
        const float va0 = vin[j0 + t],  va1 = vin[j0 + F + t],  va2 = vin[j0 + 2 * F + t];
        const float4* r0p = reinterpret_cast<const float4*>(&g_rbf[(size_t)e0 * NRBF]);
        float w00 = b0, w01 = b1, w02 = b2;
#pragma unroll
        for (int q = 0; q < NRBF / 4; q++) {
            float4 r0 = r0p[q];
            int k = 4 * q;
            w00 += r0.x * wd0[k] + r0.y * wd0[k + 1] + r0.z * wd0[k + 2] + r0.w * wd0[k + 3];
            w01 += r0.x * wd1[k] + r0.y * wd1[k + 1] + r0.z * wd1[k + 2] + r0.w * wd1[k + 3];
            w02 += r0.x * wd2[k] + r0.y * wd2[k + 1] + r0.z * wd2[k + 2] + r0.w * wd2[k + 3];
        }
        const float i00 = p00 * w00 * fc0, i01 = p01 * w01 * fc0, i02 = p02 * w02 * fc0;
        acc_s  += i01;
        acc_v0 += u0x * i02 + i00 * va0;
        acc_v1 += u0y * i02 + i00 * va1;
        acc_v2 += u0z * i02 + i00 * va2;
    }

    g_s[a * F + t] += acc_s;
    vout[a * F3 + t]         = vin[a * F3 + t]         + acc_v0;
    vout[a * F3 + F + t]     = vin[a * F3 + F + t]     + acc_v1;
    vout[a * F3 + 2 * F + t] = vin[a * F3 + 2 * F + t] + acc_v2;
}

// ---------------- vnorm + concat ----------------
__global__ void vnorm_cat_kernel() {
    int t = blockIdx.x * blockDim.x + threadIdx.x;
    if (t >= NA * F) return;
    int n = t / F, f = t % F;
    g_cat[n * 2 * F + f] = g_s[t];
    float a = g_vv[n * F3 + f];
    float b = g_vv[n * F3 + F + f];
    float c = g_vv[n * F3 + 2 * F + f];
    g_cat[n * 2 * F + F + f] = sqrtf(a * a + b * b + c * c + 1e-12f);
}

// ---------------- gated update ----------------
__global__ void update_kernel(float* __restrict__ v) {
    int t = blockIdx.x * blockDim.x + threadIdx.x;
    if (t >= NA * F) return;
    int n = t / F, f = t % F;
    float avv = g_split[n * F3 + f];
    float asv = g_split[n * F3 + F + f];
    float ass = g_split[n * F3 + 2 * F + f];
    float dot = 0.0f;
#pragma unroll
    for (int d = 0; d < 3; d++) {
        float u = g_uv[n * F3 + d * F + f];
        float w = g_vv[n * F3 + d * F + f];
        dot += u * w;
        v[n * F3 + d * F + f] += u * avv;
    }
    g_s[t] += dot * asv + ass;
}

// ============== Tensor-core GEMM: BM=64, BN=128, BK=16, 8 warps =============
// A fp32 split in-kernel (packed bf16x2 stores); W pre-split bf16 hi/lo loaded
// as 16B vectors straight into smem (no cvt). fp32 accum.
#define WA_LD 24
#define WB_LD 136
#define WC_LD 20

template <int ACT, bool DIRECT>
__global__ void __launch_bounds__(256)
wgemm_kernel(const float* __restrict__ A,
             const __nv_bfloat16* __restrict__ Wh,
             const __nv_bfloat16* __restrict__ Wl,
             const float* __restrict__ bias, float* __restrict__ C,
             int M, int N, int K) {
    constexpr int BM = 64, BN = 128, BK = 16;
    __shared__ __nv_bfloat16 As_hi[BM][WA_LD];
    __shared__ __nv_bfloat16 As_lo[BM][WA_LD];
    __shared__ __nv_bfloat16 Bs_hi[BK][WB_LD];
    __shared__ __nv_bfloat16 Bs_lo[BK][WB_LD];
    __shared__ float cstage[8][16 * WC_LD];

    const int tid = threadIdx.x;
    const int wid = tid >> 5;
    const int m0 = blockIdx.y * BM, n0 = blockIdx.x * BN;

    const int arow = tid >> 2, ak = (tid & 3) << 2;
    const bool aOK = (m0 + arow < M);
    const int brow = tid >> 4, bcol = (tid & 15) << 3;

    wmma::fragment<wmma::accumulator, 16, 16, 16, float> c[2][2];
#pragma unroll
    for (int i = 0; i < 2; i++)
#pragma unroll
        for (int j = 0; j < 2; j++)
            wmma::fill_fragment(c[i][j], 0.0f);

    const int wm = (wid >> 2) * 32;
    const int wn = (wid & 3) * 32;

    const int nk = K / BK;
    for (int kt = 0; kt < nk; kt++) {
        const int k0 = kt * BK;
        {
            float buf[4];
            if (aOK) {
                *reinterpret_cast<float4*>(buf) =
                    *reinterpret_cast<const float4*>(A + (size_t)(m0 + arow) * K + k0 + ak);
            } else {
#pragma unroll
                for (int q = 0; q < 4; q++) buf[q] = 0.f;
            }
            __nv_bfloat16 h0 = __float2bfloat16(buf[0]);
            __nv_bfloat16 h1 = __float2bfloat16(buf[1]);
            __nv_bfloat16 h2 = __float2bfloat16(buf[2]);
            __nv_bfloat16 h3 = __float2bfloat16(buf[3]);
            __nv_bfloat162 hp0; hp0.x = h0; hp0.y = h1;
            __nv_bfloat162 hp1; hp1.x = h2; hp1.y = h3;
            __nv_bfloat162 lp0;
            lp0.x = __float2bfloat16(buf[0] - __bfloat162float(h0));
            lp0.y = __float2bfloat16(buf[1] - __bfloat162float(h1));
            __nv_bfloat162 lp1;
            lp1.x = __float2bfloat16(buf[2] - __bfloat162float(h2));
            lp1.y = __float2bfloat16(buf[3] - __bfloat162float(h3));
            *reinterpret_cast<__nv_bfloat162*>(&As_hi[arow][ak])     = hp0;
            *reinterpret_cast<__nv_bfloat162*>(&As_hi[arow][ak + 2]) = hp1;
            *reinterpret_cast<__nv_bfloat162*>(&As_lo[arow][ak])     = lp0;
            *reinterpret_cast<__nv_bfloat162*>(&As_lo[arow][ak + 2]) = lp1;
        }
        {
            const size_t woff = (size_t)(k0 + brow) * N + n0 + bcol;
            *reinterpret_cast<uint4*>(&Bs_hi[brow][bcol]) =
                *reinterpret_cast<const uint4*>(Wh + woff);
            *reinterpret_cast<uint4*>(&Bs_lo[brow][bcol]) =
                *reinterpret_cast<const uint4*>(Wl + woff);
        }
        __syncthreads();

        wmma::fragment<wmma::matrix_a, 16, 16, 16, __nv_bfloat16, wmma::row_major> ah[2], al[2];
        wmma::fragment<wmma::matrix_b, 16, 16, 16, __nv_bfloat16, wmma::row_major> bh[2], bl[2];
#pragma unroll
        for (int i = 0; i < 2; i++) {
            wmma::load_matrix_sync(ah[i], &As_hi[wm + i * 16][0], WA_LD);
            wmma::load_matrix_sync(al[i], &As_lo[wm + i * 16][0], WA_LD);
        }
#pragma unroll
        for (int j = 0; j < 2; j++) {
            wmma::load_matrix_sync(bh[j], &Bs_hi[0][wn + j * 16], WB_LD);
            wmma::load_matrix_sync(bl[j], &Bs_lo[0][wn + j * 16], WB_LD);
        }
#pragma unroll
        for (int i = 0; i < 2; i++)
#pragma unroll
            for (int j = 0; j < 2; j++) {
                wmma::mma_sync(c[i][j], ah[i], bh[j], c[i][j]);
                wmma::mma_sync(c[i][j], ah[i], bl[j], c[i][j]);
                wmma::mma_sync(c[i][j], al[i], bh[j], c[i][j]);
            }
        __syncthreads();
    }

    const int lane = tid & 31;
#pragma unroll
    for (int i = 0; i < 2; i++) {
        const int grow0 = m0 + wm + i * 16;
#pragma unroll
        for (int j = 0; j < 2; j++) {
            const int gcol0 = n0 + wn + j * 16;
            if (DIRECT && grow0 + 16 <= M) {
                wmma::store_matrix_sync(C + (size_t)grow0 * N + gcol0, c[i][j], N,
                                        wmma::mem_row_major);
            } else {
                wmma::store_matrix_sync(&cstage[wid][0], c[i][j], WC_LD, wmma::mem_row_major);
                __syncwarp();
#pragma unroll
                for (int e = 0; e < 8; e++) {
                    int el = e * 32 + lane;
                    int r = el >> 4, cc = el & 15;
                    int grow = grow0 + r;
                    if (grow < M) {
                        int gcol = gcol0 + cc;
                        float x = cstage[wid][r * WC_LD + cc] + (bias ? bias[gcol] : 0.f);
                        if (ACT == 1) x = silu_f(x);
                        C[(size_t)grow * N + gcol] = x;
                    }
                }
                __syncwarp();
            }
        }
    }
}

// ---------------- fp32 SGEMM 64x128 (readout N=64 only) ----------------
template <int ACT>
__global__ void __launch_bounds__(128)
sgemm64_kernel(const float* __restrict__ A, const float* __restrict__ W,
               const float* __restrict__ bias, float* __restrict__ C,
               int M, int N, int K) {
    constexpr int BM = 64, BN = 128, BK = 8;
    __shared__ float As[2][BK][BM];
    __shared__ float Bs[2][BK][BN];
    const int tid = threadIdx.x;
    const int m0 = blockIdx.y * BM, n0 = blockIdx.x * BN;
    const int arow = tid >> 1, acol = (tid & 1) << 2;
    const int brow = tid >> 4, bcol = (tid & 15) << 3;
    const int tx = tid & 15, ty = tid >> 4;

    float acc[8][8] = {};
    float4 aR, bR0, bR1;
    const int gmA = m0 + arow;
    const bool aOK = (gmA < M);
    const bool bOK0 = (n0 + bcol < N);
    const bool bOK1 = (n0 + bcol + 4 < N);

    aR = aOK ? *reinterpret_cast<const float4*>(A + (size_t)gmA * K + acol)
             : make_float4(0.f, 0.f, 0.f, 0.f);
    bR0 = bOK0 ? *reinterpret_cast<const float4*>(W + (size_t)brow * N + n0 + bcol)
               : make_float4(0.f, 0.f, 0.f, 0.f);
    bR1 = bOK1 ? *reinterpret_cast<const float4*>(W + (size_t)brow * N + n0 + bcol + 4)
               : make_float4(0.f, 0.f, 0.f, 0.f);
    As[0][acol + 0][arow] = aR.x;
    As[0][acol + 1][arow] = aR.y;
    As[0][acol + 2][arow] = aR.z;
    As[0][acol + 3][arow] = aR.w;
    *reinterpret_cast<float4*>(&Bs[0][brow][bcol]) = bR0;
    *reinterpret_cast<float4*>(&Bs[0][brow][bcol + 4]) = bR1;
    __syncthreads();

    const int nk = K / BK;
    for (int kt = 0; kt < nk; kt++) {
        const int buf = kt & 1;
        if (kt + 1 < nk) {
            int k0 = (kt + 1) * BK;
            aR = aOK ? *reinterpret_cast<const float4*>(A + (size_t)gmA * K + k0 + acol)
                     : make_float4(0.f, 0.f, 0.f, 0.f);
            bR0 = bOK0 ? *reinterpret_cast<const float4*>(W + (size_t)(k0 + brow) * N + n0 + bcol)
                       : make_float4(0.f, 0.f, 0.f, 0.f);
            bR1 = bOK1 ? *reinterpret_cast<const float4*>(W + (size_t)(k0 + brow) * N + n0 + bcol + 4)
                       : make_float4(0.f, 0.f, 0.f, 0.f);
        }
#pragma unroll
        for (int kk = 0; kk < BK; kk++) {
            float ra[8], rb[8];
            *reinterpret_cast<float4*>(&ra[0]) = *reinterpret_cast<const float4*>(&As[buf][kk][ty * 8]);
            *reinterpret_cast<float4*>(&ra[4]) = *reinterpret_cast<const float4*>(&As[buf][kk][ty * 8 + 4]);
            *reinterpret_cast<float4*>(&rb[0]) = *reinterpret_cast<const float4*>(&Bs[buf][kk][tx * 8]);
            *reinterpret_cast<float4*>(&rb[4]) = *reinterpret_cast<const float4*>(&Bs[buf][kk][tx * 8 + 4]);
#pragma unroll
            for (int r = 0; r < 8; r++)
#pragma unroll
                for (int c = 0; c < 8; c++)
                    acc[r][c] += ra[r] * rb[c];
        }
        if (kt + 1 < nk) {
            const int nb = buf ^ 1;
            As[nb][acol + 0][arow] = aR.x;
            As[nb][acol + 1][arow] = aR.y;
            As[nb][acol + 2][arow] = aR.z;
            As[nb][acol + 3][arow] = aR.w;
            *reinterpret_cast<float4*>(&Bs[nb][brow][bcol]) = bR0;
            *reinterpret_cast<float4*>(&Bs[nb][brow][bcol + 4]) = bR1;
            __syncthreads();
        }
    }

#pragma unroll
    for (int r = 0; r < 8; r++) {
        int row = m0 + ty * 8 + r;
        if (row >= M) continue;
#pragma unroll
        for (int cc = 0; cc < 2; cc++) {
            int col = n0 + tx * 8 + cc * 4;
            if (col >= N) continue;
            float4 o;
            o.x = acc[r][cc * 4 + 0] + (bias ? bias[col + 0] : 0.f);
            o.y = acc[r][cc * 4 + 1] + (bias ? bias[col + 1] : 0.f);
            o.z = acc[r][cc * 4 + 2] + (bias ? bias[col + 2] : 0.f);
            o.w = acc[r][cc * 4 + 3] + (bias ? bias[col + 3] : 0.f);
            if (ACT == 1) {
                o.x = silu_f(o.x); o.y = silu_f(o.y);
                o.z = silu_f(o.z); o.w = silu_f(o.w);
            }
            *reinterpret_cast<float4*>(C + (size_t)row * N + col) = o;
        }
    }
}

// ---------------- final projection N=5 (warp per atom) ----------------
__global__ void out_kernel(const float* __restrict__ Wf3,
                           const float* __restrict__ bf3,
                           float* __restrict__ out) {
    int gw = (blockIdx.x * blockDim.x + threadIdx.x) >> 5;
    int lane = threadIdx.x & 31;
    if (gw >= NA) return;
    float acc[5] = {0.f, 0.f, 0.f, 0.f, 0.f};
    for (int k = lane; k < F; k += 32) {
        float h = g_t[gw * F + k];
#pragma unroll
        for (int o = 0; o < 5; o++) acc[o] += h * Wf3[k * 5 + o];
    }
#pragma unroll
    for (int o = 0; o < 5; o++) {
#pragma unroll
        for (int off = 16; off > 0; off >>= 1)
            acc[o] += __shfl_xor_sync(0xffffffffu, acc[o], off);
    }
    if (lane == 0) {
#pragma unroll
        for (int o = 0; o < 5; o++) out[gw * 5 + o] = acc[o] + bf3[o];
    }
}

// ---------------- host driver ----------------
static void* sym_addr_raw(const void* symbol) {
    void* p = nullptr;
    cudaGetSymbolAddress(&p, symbol);
    return p;
}

extern "C" void kernel_launch(void* const* d_in, const int* in_sizes, int n_in,
                              void* d_out, int out_size) {
    const float* xyz   = (const float*)d_in[0];
    const int*   z     = (const int*)d_in[1];
    const int*   nbrs  = (const int*)d_in[2];
    const float* embed = (const float*)d_in[3];
    const float* W1  = (const float*)d_in[4];
    const float* b1  = (const float*)d_in[5];
    const float* W2  = (const float*)d_in[6];
    const float* b2  = (const float*)d_in[7];
    const float* Wd  = (const float*)d_in[8];
    const float* bd  = (const float*)d_in[9];
    const float* U   = (const float*)d_in[10];
    const float* V   = (const float*)d_in[11];
    const float* Ws1 = (const float*)d_in[12];
    const float* bs1 = (const float*)d_in[13];
    const float* Ws2 = (const float*)d_in[14];
    const float* bs2 = (const float*)d_in[15];
    const float* Wr1 = (const float*)d_in[16];
    const float* br1 = (const float*)d_in[17];
    const float* Wr2 = (const float*)d_in[18];
    const float* br2 = (const float*)d_in[19];
    const float* Wf1 = (const float*)d_in[20];
    const float* bf1 = (const float*)d_in[21];
    const float* Wf2 = (const float*)d_in[22];
    const float* bf2 = (const float*)d_in[23];
    const float* Wf3 = (const float*)d_in[24];
    const float* bf3 = (const float*)d_in[25];
    float* out = (float*)d_out;

    float* s     = (float*)sym_addr_raw(g_s);
    float* va    = (float*)sym_addr_raw(g_va);
    float* vb    = (float*)sym_addr_raw(g_vb);
    float* t     = (float*)sym_addr_raw(g_t);
    float* phi   = (float*)sym_addr_raw(g_phi);
    float* uv    = (float*)sym_addr_raw(g_uv);
    float* vv    = (float*)sym_addr_raw(g_vv);
    float* cat   = (float*)sym_addr_raw(g_cat);
    float* split = (float*)sym_addr_raw(g_split);
    float* fea   = (float*)sym_addr_raw(g_fea);
    __nv_bfloat16* wh = (__nv_bfloat16*)sym_addr_raw(g_wh);
    __nv_bfloat16* wl = (__nv_bfloat16*)sym_addr_raw(g_wl);

    const int TPB = 256;
    dim3 w313_n128(1, 313);
    dim3 w313_n384(3, 313);
    dim3 w938_n128(1, 938);
    dim3 g313_n64(1, 313);

    wconv_all_kernel<<<(W_TOTAL + TPB - 1) / TPB, TPB>>>(W1, W2, U, V, Ws1, Ws2, Wr1, Wf1, Wf2);
    zero_cnt_kernel<<<(NA + 1 + TPB - 1) / TPB, TPB>>>();
    edge_geom_kernel<<<(NE + TPB - 1) / TPB, TPB>>>(xyz, nbrs);
    scan_kernel<<<1, 1024>>>();
    csr_fill_kernel<<<(NE + TPB - 1) / TPB, TPB>>>(nbrs);
    embed_init_kernel<<<(NA * F3 + TPB - 1) / TPB, TPB>>>(z, embed);

    for (int l = 0; l < NCONV; l++) {
        float* vin  = (l & 1) ? vb : va;
        float* vout = (l & 1) ? va : vb;

        wgemm_kernel<1, false><<<w313_n128, 256>>>(s, wh + OFF_W1 + l * F * F, wl + OFF_W1 + l * F * F,
                                                   b1 + l * F, t, NA, F, F);
        wgemm_kernel<0, false><<<w313_n384, 256>>>(t, wh + OFF_W2 + l * F * F3, wl + OFF_W2 + l * F * F3,
                                                   b2 + l * F3, phi, NA, F3, F);

        edge_gather_kernel<<<NA, 128>>>(nbrs, Wd + l * NRBF * F3, bd + l * F3, vin, vout);

        wgemm_kernel<0, true><<<w938_n128, 256>>>(vout, wh + OFF_U + l * F * F, wl + OFF_U + l * F * F,
                                                  nullptr, uv, NA * 3, F, F);
        wgemm_kernel<0, true><<<w938_n128, 256>>>(vout, wh + OFF_V + l * F * F, wl + OFF_V + l * F * F,
                                                  nullptr, vv, NA * 3, F, F);

        vnorm_cat_kernel<<<(NA * F + TPB - 1) / TPB, TPB>>>();

        wgemm_kernel<1, false><<<w313_n128, 256>>>(cat, wh + OFF_WS1 + l * 2 * F * F, wl + OFF_WS1 + l * 2 * F * F,
                                                   bs1 + l * F, t, NA, F, 2 * F);
        wgemm_kernel<0, false><<<w313_n384, 256>>>(t, wh + OFF_WS2 + l * F * F3, wl + OFF_WS2 + l * F * F3,
                                                   bs2 + l * F3, split, NA, F3, F);

        update_kernel<<<(NA * F + TPB - 1) / TPB, TPB>>>(vout);
    }

    wgemm_kernel<1, false><<<w313_n128, 256>>>(s, wh + OFF_WR1, wl + OFF_WR1, br1, t, NA, F, F);
    sgemm64_kernel<0><<<g313_n64, 128>>>(t, Wr2, br2, fea, NA, 64, F);
    wgemm_kernel<1, false><<<w313_n128, 256>>>(fea, wh + OFF_WF1, wl + OFF_WF1, bf1, phi, NA, F, 64);
    wgemm_kernel<1, false><<<w313_n128, 256>>>(phi, wh + OFF_WF2, wl + OFF_WF2, bf2, t, NA, F, F);
    out_kernel<<<(NA * 32 + TPB - 1) / TPB, TPB>>>(Wf3, bf3, out);
}